// round 10
// baseline (speedup 1.0000x reference)
#include <cuda_runtime.h>
#include <cuda_bf16.h>
#include <cstdint>
#include <cstddef>

#define B_  8
#define N_  2048
#define LDF 512

// ---------------- scratch (device globals: allocation-free) ----------------
__device__ __align__(16) float g_X0[B_ * N_ * 3];
__device__ __align__(16) float g_F [B_ * N_ * LDF];      // concat features [b][n][512]
__device__ __align__(16) float g_Z [B_ * N_ * LDF];      // z = W' x, rows [m][2O]
__device__ __align__(16) float g_SQ[B_ * N_];
__device__ __align__(16) int   g_ID[B_ * N_ * 4];
__device__ __align__(16) float g_CV[B_ * N_ * 64];       // knn candidate values
__device__ __align__(16) int   g_CI[B_ * N_ * 64];       // knn candidate indices
__device__ __align__(16) float g_WPf[512 * 128];         // packed W' fp32 (2O x C)
__device__ __align__(16) __nv_bfloat16 g_Xb [B_ * N_ * 1536]; // split, pattern A
__device__ __align__(16) __nv_bfloat16 g_Xb2[B_ * N_ * 384];  // split, pattern B (knn keys)
__device__ __align__(16) __nv_bfloat16 g_Wb [512 * 1536];     // split weights, pattern B

__device__ __forceinline__ uint32_t s2u(const void* p) {
    uint32_t a;
    asm("{ .reg .u64 t; cvta.to.shared.u64 t, %1; cvt.u32.u64 %0, t; }" : "=r"(a) : "l"(p));
    return a;
}
// ---- cp.async helpers ----
__device__ __forceinline__ void cp16(uint32_t dst, const void* src) {
    asm volatile("cp.async.cg.shared.global [%0], [%1], 16;" :: "r"(dst), "l"(src));
}
#define CP_COMMIT() asm volatile("cp.async.commit_group;" ::: "memory")
#define CP_WAIT1()  asm volatile("cp.async.wait_group 1;" ::: "memory")

// ---------------- transpose x (B,3,N) -> X0 [b][n][3] ----------------
__global__ void tr_x0_k(const float* __restrict__ x, float* __restrict__ X0)
{
    int t = blockIdx.x * blockDim.x + threadIdx.x;
    const int tot = B_ * 3 * N_;
    if (t >= tot) return;
    int b = t / (3 * N_);
    int r = t % (3 * N_);
    int c = r / N_;
    int n = r % N_;
    X0[((size_t)b * N_ + n) * 3 + c] = x[t];
}

// ---------------- squared norms ----------------
__global__ void sqnorm_k(const float* __restrict__ X, int ldx, int C,
                         float* __restrict__ sq)
{
    int w    = (blockIdx.x * blockDim.x + threadIdx.x) >> 5;
    int lane = threadIdx.x & 31;
    if (w >= B_ * N_) return;
    const float* r = X + (size_t)w * ldx;
    float s = 0.f;
    for (int c = lane; c < C; c += 32) { float v = r[c]; s += v * v; }
    #pragma unroll
    for (int o = 16; o; o >>= 1) s += __shfl_xor_sync(0xffffffffu, s, o);
    if (lane == 0) sq[w] = s;
}

// ---------------- top-D insertion (value desc, tie: lower index) ----------
template<int D>
__device__ __forceinline__ void topD_insert(float d, int id, float (&v)[D], int (&ix)[D])
{
    if (d > v[D-1] || (d == v[D-1] && id < ix[D-1])) {
        v[D-1] = d; ix[D-1] = id;
        #pragma unroll
        for (int s = D-1; s > 0; s--) {
            if (v[s] > v[s-1] || (v[s] == v[s-1] && ix[s] < ix[s-1])) {
                float tv = v[s]; v[s] = v[s-1]; v[s-1] = tv;
                int   ti = ix[s]; ix[s] = ix[s-1]; ix[s-1] = ti;
            } else break;
        }
    }
}
__device__ __forceinline__ void top4_insert(float d, int id, float (&v)[4], int (&ix)[4])
{ topD_insert<4>(d, id, v, ix); }

// ---------------- fused KNN for C=3 (fp32-exact) --------------------------
__global__ __launch_bounds__(256) void knn3_kernel(const float* __restrict__ X,
                                                   const float* __restrict__ sq,
                                                   int* __restrict__ out_idx)
{
    constexpr int C = 3, QROW = 68;
    __shared__ __align__(16) float pool[64 * 64 * 2];
    float* Qs = pool;
    float* Ks = pool + C * QROW;

    const int b  = blockIdx.y;
    const int q0 = blockIdx.x * 64;
    const int t  = threadIdx.x;
    const int tx = t & 15, ty = t >> 4;
    const size_t rb = (size_t)b * N_;

    for (int f = t; f < 64 * C; f += 256) {
        int c = f % C, m = f / C;
        Qs[c*QROW + m] = X[(rb + q0 + m) * 3 + c];
    }

    float sqq[4];
    #pragma unroll
    for (int i = 0; i < 4; i++) sqq[i] = sq[rb + q0 + ty*4 + i];

    float bv[4][4]; int bix[4][4];
    #pragma unroll
    for (int i = 0; i < 4; i++)
        #pragma unroll
        for (int j = 0; j < 4; j++) { bv[i][j] = -3.4e38f; bix[i][j] = 0x7fffffff; }

    for (int kb = 0; kb < N_; kb += 64) {
        float acc[4][4];
        #pragma unroll
        for (int i = 0; i < 4; i++)
            #pragma unroll
            for (int j = 0; j < 4; j++) acc[i][j] = 0.f;

        __syncthreads();
        for (int f = t; f < 64 * C; f += 256) {
            int c = f % C, m = f / C;
            Ks[c*QROW + m] = X[(rb + kb + m) * 3 + c];
        }
        __syncthreads();
        #pragma unroll
        for (int c = 0; c < C; c++) {
            float4 q4 = *(const float4*)&Qs[c*QROW + ty*4];
            float4 k4 = *(const float4*)&Ks[c*QROW + tx*4];
            float qa[4] = {q4.x, q4.y, q4.z, q4.w};
            float ka[4] = {k4.x, k4.y, k4.z, k4.w};
            #pragma unroll
            for (int i = 0; i < 4; i++)
                #pragma unroll
                for (int j = 0; j < 4; j++)
                    acc[i][j] += qa[i] * ka[j];
        }

        float sqk[4];
        #pragma unroll
        for (int j = 0; j < 4; j++) sqk[j] = sq[rb + kb + tx*4 + j];

        #pragma unroll
        for (int i = 0; i < 4; i++)
            #pragma unroll
            for (int j = 0; j < 4; j++) {
                float d = 2.0f * acc[i][j] - sqq[i] - sqk[j];
                top4_insert(d, kb + tx*4 + j, bv[i], bix[i]);
            }
    }

    __syncthreads();
    float* cv = pool;
    int*   ci = (int*)(pool + 64 * 64);
    #pragma unroll
    for (int qi = 0; qi < 4; qi++) {
        int base = (ty*4 + qi) * 64 + tx * 4;
        #pragma unroll
        for (int r = 0; r < 4; r++) { cv[base + r] = bv[qi][r]; ci[base + r] = bix[qi][r]; }
    }
    __syncthreads();
    if (t < 64) {
        float v4[4]; int i4[4];
        #pragma unroll
        for (int r = 0; r < 4; r++) { v4[r] = -3.4e38f; i4[r] = 0x7fffffff; }
        for (int j = 0; j < 64; j++)
            top4_insert(cv[t*64 + j], ci[t*64 + j], v4, i4);
        int* op = out_idx + (rb + q0 + t) * 4;
        op[0] = i4[0]; op[1] = i4[1]; op[2] = i4[2]; op[3] = i4[3];
    }
}

// ---------------- HMMA helpers ----------------
__device__ __forceinline__ void ldmx4(uint32_t (&r)[4], uint32_t addr)
{
    asm volatile("ldmatrix.sync.aligned.m8n8.x4.shared.b16 {%0,%1,%2,%3}, [%4];"
                 : "=r"(r[0]), "=r"(r[1]), "=r"(r[2]), "=r"(r[3]) : "r"(addr));
}
__device__ __forceinline__ void mma16816(float (&d)[4], const uint32_t (&a)[4],
                                         uint32_t b0, uint32_t b1)
{
    asm volatile(
        "mma.sync.aligned.m16n8k16.row.col.f32.bf16.bf16.f32 "
        "{%0,%1,%2,%3}, {%4,%5,%6,%7}, {%8,%9}, {%0,%1,%2,%3};"
        : "+f"(d[0]), "+f"(d[1]), "+f"(d[2]), "+f"(d[3])
        : "r"(a[0]), "r"(a[1]), "r"(a[2]), "r"(a[3]), "r"(b0), "r"(b1));
}

// ===== symmetric HMMA KNN: one 128x128 Gram tile per CTA, both orientations
// grid.x = 136 upper-tri tile pairs, grid.y = batch.
// split expr ha*hb + ha*lb + la*hb is role-symmetric -> tile serves rows+cols.
template<int C>
__global__ __launch_bounds__(256) void knn_sym(const __nv_bfloat16* __restrict__ XA,
                                               const __nv_bfloat16* __restrict__ XB,
                                               const float* __restrict__ sq,
                                               float* __restrict__ cv,
                                               int* __restrict__ ci)
{
    constexpr int Ka    = 3 * C;
    constexpr int AKROW = Ka + 8;
    constexpr int BROW  = 40;
    constexpr int BSTG  = 128 * BROW;
    constexpr int NK    = Ka / 32;
    constexpr int TROW  = 129;          // tile row stride (floats), conflict-free
    extern __shared__ __align__(16) char sympool[];
    __nv_bfloat16* As = (__nv_bfloat16*)sympool;
    __nv_bfloat16* Bs = As + 128 * AKROW;
    float*         Ts = (float*)(Bs + 3 * BSTG);

    const int b = blockIdx.y;
    const size_t rb = (size_t)b * N_;
    // decode upper-triangular pair (ti <= tj)
    int pidx = blockIdx.x, ti = 0, span = 16;
    while (pidx >= span) { pidx -= span; ti++; span--; }
    const int tj = ti + pidx;
    const int q0 = ti * 128, k0 = tj * 128;

    const int t = threadIdx.x, wid = t >> 5, lane = t & 31;
    const int wm = wid & 1, wn = wid >> 1;
    const int gid = lane >> 2, tig = lane & 3;
    const uint32_t uA = s2u(As), uB = s2u(Bs);

    // resident query tile (block ti)
    for (int idx = t; idx < 128 * (Ka / 8); idx += 256) {
        int r = idx / (Ka / 8), c8 = idx % (Ka / 8);
        uint4 v = *(const uint4*)(XA + (rb + q0 + r) * (size_t)Ka + c8 * 8);
        *(uint4*)(As + r * AKROW + c8 * 8) = v;
    }
    __syncthreads();

    const int a_r  = wm * 64 + (lane & 15);
    const int a_c8 = (lane >> 4) * 8;
    const int b_rl = wn * 32 + ((lane >> 4) << 3) + (lane & 7);
    const int b_c8 = ((lane >> 3) & 1) * 8;
    const int br0 = t >> 2, bc4 = t & 3;

    auto kissue = [&](int ch2) {
        if (ch2 < NK) {
            int s = ch2 % 3;
            const __nv_bfloat16* p = XB + (rb + k0) * (size_t)Ka + ch2 * 32;
            uint32_t db = uB + 2u * (s * BSTG);
            cp16(db + 2u * (br0 * BROW + bc4 * 8),
                 p + (size_t)br0 * Ka + bc4 * 8);
            cp16(db + 2u * ((br0 + 64) * BROW + bc4 * 8),
                 p + (size_t)(br0 + 64) * Ka + bc4 * 8);
        }
        CP_COMMIT();
    };

    float acc[4][4][4];
    #pragma unroll
    for (int mt = 0; mt < 4; mt++)
        #pragma unroll
        for (int nt = 0; nt < 4; nt++)
            #pragma unroll
            for (int e = 0; e < 4; e++) acc[mt][nt][e] = 0.f;

    kissue(0); kissue(1);
    for (int ch = 0; ch < NK; ch++) {
        CP_WAIT1();
        __syncthreads();
        const uint32_t uBs = uB + 2u * ((ch % 3) * BSTG);
        #pragma unroll
        for (int ks = 0; ks < 32; ks += 16) {
            uint32_t af[4][4], bf[2][4];
            #pragma unroll
            for (int mt = 0; mt < 4; mt++)
                ldmx4(af[mt], uA + 2u * ((a_r + mt * 16) * AKROW + ch * 32 + ks + a_c8));
            #pragma unroll
            for (int n2 = 0; n2 < 2; n2++)
                ldmx4(bf[n2], uBs + 2u * ((b_rl + n2 * 16) * BROW + ks + b_c8));
            #pragma unroll
            for (int mt = 0; mt < 4; mt++)
                #pragma unroll
                for (int nt = 0; nt < 4; nt++)
                    mma16816(acc[mt][nt], af[mt],
                             bf[nt >> 1][(nt & 1) * 2], bf[nt >> 1][(nt & 1) * 2 + 1]);
        }
        kissue(ch + 2);
    }

    // dump tile to smem
    #pragma unroll
    for (int mt = 0; mt < 4; mt++) {
        int r = wm * 64 + mt * 16 + gid;
        #pragma unroll
        for (int nt = 0; nt < 4; nt++) {
            int c = wn * 32 + nt * 8 + tig * 2;
            Ts[r * TROW + c]           = acc[mt][nt][0];
            Ts[r * TROW + c + 1]       = acc[mt][nt][1];
            Ts[(r + 8) * TROW + c]     = acc[mt][nt][2];
            Ts[(r + 8) * TROW + c + 1] = acc[mt][nt][3];
        }
    }
    __syncthreads();

    if (t < 128) {
        // row pass: queries block ti, keys block tj
        const int lr = t;
        const float sqq = sq[rb + q0 + lr];
        float v4[4]; int i4[4];
        #pragma unroll
        for (int r = 0; r < 4; r++) { v4[r] = -3.4e38f; i4[r] = 0x7fffffff; }
        for (int c = 0; c < 128; c++) {
            float d = 2.0f * Ts[lr * TROW + c] - sqq - sq[rb + k0 + c];
            top4_insert(d, k0 + c, v4, i4);
        }
        size_t base = (rb + q0 + lr) * 64 + tj * 4;
        #pragma unroll
        for (int r = 0; r < 4; r++) { cv[base + r] = v4[r]; ci[base + r] = i4[r]; }
    } else if (ti < tj) {
        // col pass: queries block tj, keys block ti (same tile values)
        const int u = t - 128;
        const float squ = sq[rb + k0 + u];
        float v4[4]; int i4[4];
        #pragma unroll
        for (int r = 0; r < 4; r++) { v4[r] = -3.4e38f; i4[r] = 0x7fffffff; }
        for (int r = 0; r < 128; r++) {
            float d = 2.0f * Ts[r * TROW + u] - squ - sq[rb + q0 + r];
            top4_insert(d, q0 + r, v4, i4);
        }
        size_t base = (rb + k0 + u) * 64 + ti * 4;
        #pragma unroll
        for (int r = 0; r < 4; r++) { cv[base + r] = v4[r]; ci[base + r] = i4[r]; }
    }
}

static inline int knnsym_smem(int C) {
    int Ka = 3 * C;
    return 128 * (Ka + 8) * 2 + 3 * 128 * 40 * 2 + 128 * 129 * 4;
}

// ---- merge 64 candidates -> top8 (approx), then exact fp32 fixup -> top4 --
__global__ void merge_fixup_k(const float* __restrict__ X, int ldx, int C,
                              const float* __restrict__ sq,
                              const float* __restrict__ cv,
                              const int* __restrict__ ci,
                              int* __restrict__ out)
{
    __shared__ int sh[8][8];
    int wl = threadIdx.x >> 5;
    int w = blockIdx.x * 8 + wl;
    int lane = threadIdx.x & 31;
    if (w >= B_ * N_) return;
    size_t rb = (size_t)(w >> 11) << 11;        // N_ = 2048
    if (lane == 0) {
        float v8[8]; int i8[8];
        #pragma unroll
        for (int r = 0; r < 8; r++) { v8[r] = -3.4e38f; i8[r] = 0x7fffffff; }
        const float* pv = cv + (size_t)w * 64;
        const int*   pi = ci + (size_t)w * 64;
        for (int j = 0; j < 64; j++)
            topD_insert<8>(pv[j], pi[j], v8, i8);
        #pragma unroll
        for (int r = 0; r < 8; r++) sh[wl][r] = i8[r];
    }
    __syncwarp();
    int id = 0; float d = -3.4e38f;
    if (lane < 8) {
        id = sh[wl][lane];
        const float* qp = X + (size_t)w * ldx;
        const float* kp = X + (rb + id) * ldx;
        float dot = 0.f;
        for (int c = 0; c < C; c += 4) {
            float4 a = *(const float4*)(qp + c);
            float4 b2 = *(const float4*)(kp + c);
            dot += a.x * b2.x + a.y * b2.y + a.z * b2.z + a.w * b2.w;
        }
        d = 2.0f * dot - sq[w] - sq[rb + id];
    }
    float v4[4]; int i4[4];
    #pragma unroll
    for (int r = 0; r < 4; r++) { v4[r] = -3.4e38f; i4[r] = 0x7fffffff; }
    #pragma unroll
    for (int j = 0; j < 8; j++) {
        float dj = __shfl_sync(0xffffffffu, d, j);
        int   ij = __shfl_sync(0xffffffffu, id, j);
        top4_insert(dj, ij, v4, i4);
    }
    if (lane == 0) {
        int4 o = make_int4(i4[0], i4[1], i4[2], i4[3]);
        *(int4*)(out + (size_t)w * 4) = o;
    }
}

// ---------------- pack W (O x 2C) -> W' (2O x C) ----------------
__global__ void packw_k(const float* __restrict__ W, float* __restrict__ Wp, int O, int Cc)
{
    int t = blockIdx.x * blockDim.x + threadIdx.x;
    int tot = 2 * O * Cc;
    if (t >= tot) return;
    int r = t / Cc, c = t % Cc;
    Wp[t] = (r < O) ? W[r * (2*Cc) + c] : W[(r - O) * (2*Cc) + Cc + c];
}

// ------- split fp32 -> bf16 limbs, K-expanded by term pattern --------------
__global__ void split_k(const float* __restrict__ src, int lds, int C,
                        unsigned patbits, int nT, int Kpad, int R,
                        __nv_bfloat16* __restrict__ dst)
{
    int t = blockIdx.x * blockDim.x + threadIdx.x;
    int tot = R * Kpad;
    if (t >= tot) return;
    int col = t % Kpad;
    int r   = t / Kpad;
    float v = 0.f;
    if (col < nT * C) {
        int tb = col / C, c = col - tb * C;
        float x = src[(size_t)r * lds + c];
        float h = __bfloat162float(__float2bfloat16(x));
        float m = x - h;
        int p = (patbits >> (3 * tb)) & 7;
        v = (p == 0) ? h : m;
    }
    dst[t] = __float2bfloat16(v);
}

// ---------------- SIMT NT SGEMM (precision-critical layers) ----------------
__device__ __forceinline__ void g2s_tile(float* S, const float* M, int ld,
                                         int r0, int k0, int K, int cq, int li)
{
    const float* rp = M + (size_t)(r0 + li) * ld;
    int c = k0 + cq * 4;
    float x, y, z, w;
    if (c + 3 < K && (((uintptr_t)(rp + c) & 15u) == 0)) {
        float4 v = *(const float4*)(rp + c);
        x = v.x; y = v.y; z = v.z; w = v.w;
    } else {
        x = (c + 0 < K) ? rp[c + 0] : 0.f;
        y = (c + 1 < K) ? rp[c + 1] : 0.f;
        z = (c + 2 < K) ? rp[c + 2] : 0.f;
        w = (c + 3 < K) ? rp[c + 3] : 0.f;
    }
    S[(cq*4+0)*68 + li] = x;
    S[(cq*4+1)*68 + li] = y;
    S[(cq*4+2)*68 + li] = z;
    S[(cq*4+3)*68 + li] = w;
}

__global__ __launch_bounds__(256) void gemm_nt(int K,
    const float* __restrict__ A,  int lda, size_t sA,
    const float* __restrict__ Bm, int ldb, size_t sB,
    float* __restrict__ Cm,       int ldc, size_t sC)
{
    __shared__ __align__(16) float As[16 * 68];
    __shared__ __align__(16) float Bs[16 * 68];
    const int bz = blockIdx.z;
    A  += (size_t)bz * sA;
    Bm += (size_t)bz * sB;
    Cm += (size_t)bz * sC;
    const int i0 = blockIdx.y * 64, j0 = blockIdx.x * 64;
    const int t  = threadIdx.x;
    const int tx = t & 15, ty = t >> 4;
    const int cq = t & 3,  li = t >> 2;

    float acc[4][4];
    #pragma unroll
    for (int i = 0; i < 4; i++)
        #pragma unroll
        for (int j = 0; j < 4; j++) acc[i][j] = 0.f;

    for (int k0 = 0; k0 < K; k0 += 16) {
        g2s_tile(As, A,  lda, i0, k0, K, cq, li);
        g2s_tile(Bs, Bm, ldb, j0, k0, K, cq, li);
        __syncthreads();
        #pragma unroll
        for (int c = 0; c < 16; c++) {
            float4 a4 = *(const float4*)&As[c*68 + ty*4];
            float4 b4 = *(const float4*)&Bs[c*68 + tx*4];
            float aa[4] = {a4.x, a4.y, a4.z, a4.w};
            float bb[4] = {b4.x, b4.y, b4.z, b4.w};
            #pragma unroll
            for (int i = 0; i < 4; i++)
                #pragma unroll
                for (int j = 0; j < 4; j++)
                    acc[i][j] += aa[i] * bb[j];
        }
        __syncthreads();
    }
    #pragma unroll
    for (int r = 0; r < 4; r++) {
        float4 v = make_float4(acc[r][0], acc[r][1], acc[r][2], acc[r][3]);
        *(float4*)&Cm[(size_t)(i0 + ty*4 + r) * ldc + j0 + tx*4] = v;
    }
}

// ============== HMMA bf16 NT-GEMM, cp.async 3-stage pipeline ===============
#define KC   32
#define KPAD 8
#define AROW (KC + KPAD)
#define GSTG (128 * AROW)
#define GSMEM (3 * GSTG * 2 * 2)

__global__ __launch_bounds__(256) void gemm_mma(int Ka,
    const __nv_bfloat16* __restrict__ A, int lda, size_t sA,
    const __nv_bfloat16* __restrict__ B, int ldb, size_t sB,
    float* __restrict__ D, int ldd, size_t sD)
{
    extern __shared__ __align__(16) __nv_bfloat16 gsm[];
    __nv_bfloat16* As = gsm;
    __nv_bfloat16* Bs = gsm + 3 * GSTG;
    const int bz = blockIdx.z;
    A += (size_t)bz * sA;
    B += (size_t)bz * sB;
    D += (size_t)bz * sD;
    const int i0 = blockIdx.y * 128;
    const int j0 = blockIdx.x * 128;
    const int t = threadIdx.x, wid = t >> 5, lane = t & 31;
    const int wm = wid & 1, wn = wid >> 1;
    const int gid = lane >> 2, tig = lane & 3;

    const uint32_t uA = s2u(As), uB = s2u(Bs);

    const int a_r  = wm * 64 + (lane & 15);
    const int a_c8 = (lane >> 4) * 8;
    const int b_r  = wn * 32 + ((lane >> 4) << 3) + (lane & 7);
    const int b_c8 = ((lane >> 3) & 1) * 8;

    const int gr0 = t >> 2, gc0 = t & 3;
    const int gr1 = gr0 + 64;

    float acc[4][4][4];
    #pragma unroll
    for (int mt = 0; mt < 4; mt++)
        #pragma unroll
        for (int nt = 0; nt < 4; nt++)
            #pragma unroll
            for (int e = 0; e < 4; e++) acc[mt][nt][e] = 0.f;

    const int nk = Ka / KC;

    auto issue = [&](int k2) {
        if (k2 < nk) {
            int s = k2 % 3;
            const __nv_bfloat16* Ag = A + (size_t)i0 * lda + k2 * KC;
            const __nv_bfloat16* Bg = B + (size_t)j0 * ldb + k2 * KC;
            uint32_t da = uA + 2u * (s * GSTG);
            uint32_t db = uB + 2u * (s * GSTG);
            cp16(da + 2u * (gr0 * AROW + gc0 * 8), Ag + (size_t)gr0 * lda + gc0 * 8);
            cp16(da + 2u * (gr1 * AROW + gc0 * 8), Ag + (size_t)gr1 * lda + gc0 * 8);
            cp16(db + 2u * (gr0 * AROW + gc0 * 8), Bg + (size_t)gr0 * ldb + gc0 * 8);
            cp16(db + 2u * (gr1 * AROW + gc0 * 8), Bg + (size_t)gr1 * ldb + gc0 * 8);
        }
        CP_COMMIT();
    };

    issue(0); issue(1);
    for (int k = 0; k < nk; k++) {
        CP_WAIT1();
        __syncthreads();
        const int s = k % 3;
        const uint32_t uAs = uA + 2u * (s * GSTG);
        const uint32_t uBs = uB + 2u * (s * GSTG);
        #pragma unroll
        for (int ks = 0; ks < KC; ks += 16) {
            uint32_t af[4][4], bf[2][4];
            #pragma unroll
            for (int mt = 0; mt < 4; mt++)
                ldmx4(af[mt], uAs + 2u * ((a_r + mt * 16) * AROW + ks + a_c8));
            #pragma unroll
            for (int n2 = 0; n2 < 2; n2++)
                ldmx4(bf[n2], uBs + 2u * ((b_r + n2 * 16) * AROW + ks + b_c8));
            #pragma unroll
            for (int mt = 0; mt < 4; mt++)
                #pragma unroll
                for (int nt = 0; nt < 4; nt++)
                    mma16816(acc[mt][nt], af[mt],
                             bf[nt >> 1][(nt & 1) * 2], bf[nt >> 1][(nt & 1) * 2 + 1]);
        }
        issue(k + 2);
    }

    #pragma unroll
    for (int mt = 0; mt < 4; mt++) {
        int r = i0 + wm * 64 + mt * 16 + gid;
        #pragma unroll
        for (int nt = 0; nt < 4; nt++) {
            int c = j0 + wn * 32 + nt * 8 + tig * 2;
            *(float2*)&D[(size_t)r * ldd + c]       = make_float2(acc[mt][nt][0], acc[mt][nt][1]);
            *(float2*)&D[(size_t)(r + 8) * ldd + c] = make_float2(acc[mt][nt][2], acc[mt][nt][3]);
        }
    }
}

// ---------------- gather + relu + max-over-k epilogue ---------------------
__global__ void edge_epi_k(const float* __restrict__ Z, const int* __restrict__ idx,
                           float* __restrict__ Fo, int O)
{
    const int b = blockIdx.y, n = blockIdx.x;
    const size_t rb = (size_t)b * N_;
    int4 id = *(const int4*)(idx + (rb + n) * 4);
    const size_t w = (size_t)(2 * O);
    const float* zb = Z + rb * w;
    const float* z0 = zb + (size_t)id.x * w;
    const float* z1 = zb + (size_t)id.y * w;
    const float* z2 = zb + (size_t)id.z * w;
    const float* z3 = zb + (size_t)id.w * w;
    const float* zc = zb + (size_t)n * w + O;
    float* fo = Fo + (rb + n) * LDF;
    for (int o = threadIdx.x; o < O; o += blockDim.x) {
        float m = fmaxf(fmaxf(z0[o], z1[o]), fmaxf(z2[o], z3[o]));
        fo[o] = fmaxf(m + zc[o], 0.f);
    }
}

// ---------------- orchestration ----------------
extern "C" void kernel_launch(void* const* d_in, const int* in_sizes, int n_in,
                              void* d_out, int out_size)
{
    const float* x  = (const float*)d_in[0];
    const float* W1 = (const float*)d_in[1];
    const float* W2 = (const float*)d_in[2];
    const float* W3 = (const float*)d_in[3];
    const float* W4 = (const float*)d_in[4];
    const float* W5 = (const float*)d_in[5];
    float* out = (float*)d_out;

    void* p;
    cudaGetSymbolAddress(&p, g_X0);  float* X0 = (float*)p;
    cudaGetSymbolAddress(&p, g_F );  float* F  = (float*)p;
    cudaGetSymbolAddress(&p, g_Z );  float* Z  = (float*)p;
    cudaGetSymbolAddress(&p, g_SQ);  float* SQ = (float*)p;
    cudaGetSymbolAddress(&p, g_ID);  int*   ID = (int*)p;
    cudaGetSymbolAddress(&p, g_CV);  float* CV = (float*)p;
    cudaGetSymbolAddress(&p, g_CI);  int*   CI = (int*)p;
    cudaGetSymbolAddress(&p, g_WPf); float* WPf = (float*)p;
    cudaGetSymbolAddress(&p, g_Xb);  __nv_bfloat16* Xb  = (__nv_bfloat16*)p;
    cudaGetSymbolAddress(&p, g_Xb2); __nv_bfloat16* Xb2 = (__nv_bfloat16*)p;
    cudaGetSymbolAddress(&p, g_Wb);  __nv_bfloat16* Wb  = (__nv_bfloat16*)p;

    cudaFuncSetAttribute(knn_sym<64>,
        cudaFuncAttributeMaxDynamicSharedMemorySize, knnsym_smem(64));
    cudaFuncSetAttribute(knn_sym<128>,
        cudaFuncAttributeMaxDynamicSharedMemorySize, knnsym_smem(128));
    cudaFuncSetAttribute(gemm_mma,
        cudaFuncAttributeMaxDynamicSharedMemorySize, GSMEM);

    // split patterns (3-term, 2-limb): A gets {h,h,l}, B gets {h,l,h}
    const unsigned PAT_A = 0u | (0u << 3) | (1u << 6);
    const unsigned PAT_B = 0u | (1u << 3) | (0u << 6);

    tr_x0_k<<<(B_*3*N_ + 255)/256, 256>>>(x, X0);

    // symmetric HMMA knn: split -> 136 tile-pairs -> merge64->top8 -> fixup
    auto knn_tc = [&](const float* Xin, int C) {
        int Kp = 3 * C;
        sqnorm_k<<<(B_*N_*32)/256, 256>>>(Xin, LDF, C, SQ);
        split_k<<<(B_*N_*Kp + 255)/256, 256>>>(Xin, LDF, C, PAT_A, 3, Kp, B_*N_, Xb);
        split_k<<<(B_*N_*Kp + 255)/256, 256>>>(Xin, LDF, C, PAT_B, 3, Kp, B_*N_, Xb2);
        dim3 kg(136, B_);
        if (C == 64)
            knn_sym<64> <<<kg, 256, knnsym_smem(64) >>>(Xb, Xb2, SQ, CV, CI);
        else
            knn_sym<128><<<kg, 256, knnsym_smem(128)>>>(Xb, Xb2, SQ, CV, CI);
        merge_fixup_k<<<(B_*N_)/8, 256>>>(Xin, LDF, C, SQ, CV, CI, ID);
    };

    // ---- layer 1: fp32 knn (C=3) + SIMT z-GEMM
    {
        sqnorm_k<<<(B_*N_*32)/256, 256>>>(X0, 3, 3, SQ);
        knn3_kernel<<<dim3(N_/64, B_), 256>>>(X0, SQ, ID);
        packw_k<<<(2*64*3 + 255)/256, 256>>>(W1, WPf, 64, 3);
        dim3 gg(128/64, (B_*N_)/64, 1);
        gemm_nt<<<gg, 256>>>(3, X0, 3, (size_t)0, WPf, 3, (size_t)0,
                             Z, 128, (size_t)0);
        edge_epi_k<<<dim3(N_, B_), 64>>>(Z, ID, F + 0, 64);
    }

    // ---- layers 2-3: HMMA knn + SIMT fp32 z-GEMM (z feeds next knn)
    auto layer23 = [&](const float* Xin, int C, int O, const float* W, float* Fout) {
        knn_tc(Xin, C);
        packw_k<<<(2*O*C + 255)/256, 256>>>(W, WPf, O, C);
        dim3 gg((2*O)/64, (B_*N_)/64, 1);
        gemm_nt<<<gg, 256>>>(C, Xin, LDF, (size_t)0, WPf, C, (size_t)0,
                             Z, 2*O, (size_t)0);
        edge_epi_k<<<dim3(N_, B_), O>>>(Z, ID, Fout, O);
    };
    layer23(F + 0,  64, 64,  W2, F + 64);    // x2 -> F[:, 64:128]
    layer23(F + 64, 64, 128, W3, F + 128);   // x3 -> F[:, 128:256]

    // ---- layer 4: HMMA knn + HMMA z-GEMM (Xb = PAT_A split of F+128)
    {
        const int C = 128, O = 256, Kp = 3 * C;       // 384
        knn_tc(F + 128, C);
        packw_k<<<(2*O*C + 255)/256, 256>>>(W4, WPf, O, C);
        split_k<<<(2*O*Kp + 255)/256, 256>>>(WPf, C, C, PAT_B, 3, Kp, 2*O, Wb);
        dim3 gg((2*O)/128, (B_*N_)/128, 1);
        gemm_mma<<<gg, 256, GSMEM>>>(Kp, Xb, Kp, (size_t)0, Wb, Kp, (size_t)0,
                                     Z, 2*O, (size_t)0);
        edge_epi_k<<<dim3(N_, B_), O>>>(Z, ID, F + 256, O);
    }

    // ---- final: out[b][o][n] = W5 · concat-features, HMMA
    {
        const int C = 512, Kp = 3 * C;                // 1536
        split_k<<<(512*Kp + 255)/256, 256>>>(W5, C, C, PAT_B, 3, Kp, 512, Wb);
        split_k<<<(B_*N_*Kp + 255)/256, 256>>>(F, LDF, C, PAT_A, 3, Kp, B_*N_, Xb);
        dim3 fg(N_/128, 512/128, B_);
        gemm_mma<<<fg, 256, GSMEM>>>(Kp,
                                     Wb, Kp, (size_t)0,
                                     Xb, Kp, (size_t)N_ * Kp,
                                     out, N_, (size_t)512 * N_);
    }
}

// round 11
// speedup vs baseline: 1.1114x; 1.1114x over previous
#include <cuda_runtime.h>
#include <cuda_bf16.h>
#include <cstdint>
#include <cstddef>

#define B_  8
#define N_  2048
#define LDF 512

// ---------------- scratch (device globals: allocation-free) ----------------
__device__ __align__(16) float g_X0[B_ * N_ * 3];
__device__ __align__(16) float g_F [B_ * N_ * LDF];      // concat features [b][n][512]
__device__ __align__(16) float g_Z [B_ * N_ * LDF];      // z = W' x, rows [m][2O]
__device__ __align__(16) float g_SQ[B_ * N_];
__device__ __align__(16) int   g_ID[B_ * N_ * 4];
__device__ __align__(16) int   g_C8[B_ * N_ * 8];        // knn top-8 candidates
__device__ __align__(16) float g_WPf[512 * 128];         // packed W' fp32 (2O x C)
__device__ __align__(16) __nv_bfloat16 g_Xb [B_ * N_ * 1536]; // split, pattern A
__device__ __align__(16) __nv_bfloat16 g_Xb2[B_ * N_ * 384];  // split, pattern B (knn keys)
__device__ __align__(16) __nv_bfloat16 g_Wb [512 * 1536];     // split weights, pattern B

__device__ __forceinline__ uint32_t s2u(const void* p) {
    uint32_t a;
    asm("{ .reg .u64 t; cvta.to.shared.u64 t, %1; cvt.u32.u64 %0, t; }" : "=r"(a) : "l"(p));
    return a;
}
// ---- cp.async helpers ----
__device__ __forceinline__ void cp16(uint32_t dst, const void* src) {
    asm volatile("cp.async.cg.shared.global [%0], [%1], 16;" :: "r"(dst), "l"(src));
}
#define CP_COMMIT() asm volatile("cp.async.commit_group;" ::: "memory")
#define CP_WAIT1()  asm volatile("cp.async.wait_group 1;" ::: "memory")

// ---------------- transpose x (B,3,N) -> X0 [b][n][3] ----------------
__global__ void tr_x0_k(const float* __restrict__ x, float* __restrict__ X0)
{
    int t = blockIdx.x * blockDim.x + threadIdx.x;
    const int tot = B_ * 3 * N_;
    if (t >= tot) return;
    int b = t / (3 * N_);
    int r = t % (3 * N_);
    int c = r / N_;
    int n = r % N_;
    X0[((size_t)b * N_ + n) * 3 + c] = x[t];
}

// ---------------- squared norms ----------------
__global__ void sqnorm_k(const float* __restrict__ X, int ldx, int C,
                         float* __restrict__ sq)
{
    int w    = (blockIdx.x * blockDim.x + threadIdx.x) >> 5;
    int lane = threadIdx.x & 31;
    if (w >= B_ * N_) return;
    const float* r = X + (size_t)w * ldx;
    float s = 0.f;
    for (int c = lane; c < C; c += 32) { float v = r[c]; s += v * v; }
    #pragma unroll
    for (int o = 16; o; o >>= 1) s += __shfl_xor_sync(0xffffffffu, s, o);
    if (lane == 0) sq[w] = s;
}

// ---------------- top-D insertion (value desc, tie: lower index) ----------
template<int D>
__device__ __forceinline__ void topD_insert(float d, int id, float (&v)[D], int (&ix)[D])
{
    if (d > v[D-1] || (d == v[D-1] && id < ix[D-1])) {
        v[D-1] = d; ix[D-1] = id;
        #pragma unroll
        for (int s = D-1; s > 0; s--) {
            if (v[s] > v[s-1] || (v[s] == v[s-1] && ix[s] < ix[s-1])) {
                float tv = v[s]; v[s] = v[s-1]; v[s-1] = tv;
                int   ti = ix[s]; ix[s] = ix[s-1]; ix[s-1] = ti;
            } else break;
        }
    }
}
__device__ __forceinline__ void top4_insert(float d, int id, float (&v)[4], int (&ix)[4])
{ topD_insert<4>(d, id, v, ix); }

// ---------------- fused KNN for C=3 (fp32-exact) --------------------------
__global__ __launch_bounds__(256) void knn3_kernel(const float* __restrict__ X,
                                                   const float* __restrict__ sq,
                                                   int* __restrict__ out_idx)
{
    constexpr int C = 3, QROW = 68;
    __shared__ __align__(16) float pool[64 * 64 * 2];
    float* Qs = pool;
    float* Ks = pool + C * QROW;

    const int b  = blockIdx.y;
    const int q0 = blockIdx.x * 64;
    const int t  = threadIdx.x;
    const int tx = t & 15, ty = t >> 4;
    const size_t rb = (size_t)b * N_;

    for (int f = t; f < 64 * C; f += 256) {
        int c = f % C, m = f / C;
        Qs[c*QROW + m] = X[(rb + q0 + m) * 3 + c];
    }

    float sqq[4];
    #pragma unroll
    for (int i = 0; i < 4; i++) sqq[i] = sq[rb + q0 + ty*4 + i];

    float bv[4][4]; int bix[4][4];
    #pragma unroll
    for (int i = 0; i < 4; i++)
        #pragma unroll
        for (int j = 0; j < 4; j++) { bv[i][j] = -3.4e38f; bix[i][j] = 0x7fffffff; }

    for (int kb = 0; kb < N_; kb += 64) {
        float acc[4][4];
        #pragma unroll
        for (int i = 0; i < 4; i++)
            #pragma unroll
            for (int j = 0; j < 4; j++) acc[i][j] = 0.f;

        __syncthreads();
        for (int f = t; f < 64 * C; f += 256) {
            int c = f % C, m = f / C;
            Ks[c*QROW + m] = X[(rb + kb + m) * 3 + c];
        }
        __syncthreads();
        #pragma unroll
        for (int c = 0; c < C; c++) {
            float4 q4 = *(const float4*)&Qs[c*QROW + ty*4];
            float4 k4 = *(const float4*)&Ks[c*QROW + tx*4];
            float qa[4] = {q4.x, q4.y, q4.z, q4.w};
            float ka[4] = {k4.x, k4.y, k4.z, k4.w};
            #pragma unroll
            for (int i = 0; i < 4; i++)
                #pragma unroll
                for (int j = 0; j < 4; j++)
                    acc[i][j] += qa[i] * ka[j];
        }

        float sqk[4];
        #pragma unroll
        for (int j = 0; j < 4; j++) sqk[j] = sq[rb + kb + tx*4 + j];

        #pragma unroll
        for (int i = 0; i < 4; i++)
            #pragma unroll
            for (int j = 0; j < 4; j++) {
                float d = 2.0f * acc[i][j] - sqq[i] - sqk[j];
                top4_insert(d, kb + tx*4 + j, bv[i], bix[i]);
            }
    }

    __syncthreads();
    float* cv = pool;
    int*   ci = (int*)(pool + 64 * 64);
    #pragma unroll
    for (int qi = 0; qi < 4; qi++) {
        int base = (ty*4 + qi) * 64 + tx * 4;
        #pragma unroll
        for (int r = 0; r < 4; r++) { cv[base + r] = bv[qi][r]; ci[base + r] = bix[qi][r]; }
    }
    __syncthreads();
    if (t < 64) {
        float v4[4]; int i4[4];
        #pragma unroll
        for (int r = 0; r < 4; r++) { v4[r] = -3.4e38f; i4[r] = 0x7fffffff; }
        for (int j = 0; j < 64; j++)
            top4_insert(cv[t*64 + j], ci[t*64 + j], v4, i4);
        int* op = out_idx + (rb + q0 + t) * 4;
        op[0] = i4[0]; op[1] = i4[1]; op[2] = i4[2]; op[3] = i4[3];
    }
}

// ---------------- HMMA helpers ----------------
__device__ __forceinline__ void ldmx4(uint32_t (&r)[4], uint32_t addr)
{
    asm volatile("ldmatrix.sync.aligned.m8n8.x4.shared.b16 {%0,%1,%2,%3}, [%4];"
                 : "=r"(r[0]), "=r"(r[1]), "=r"(r[2]), "=r"(r[3]) : "r"(addr));
}
__device__ __forceinline__ void mma16816(float (&d)[4], const uint32_t (&a)[4],
                                         uint32_t b0, uint32_t b1)
{
    asm volatile(
        "mma.sync.aligned.m16n8k16.row.col.f32.bf16.bf16.f32 "
        "{%0,%1,%2,%3}, {%4,%5,%6,%7}, {%8,%9}, {%0,%1,%2,%3};"
        : "+f"(d[0]), "+f"(d[1]), "+f"(d[2]), "+f"(d[3])
        : "r"(a[0]), "r"(a[1]), "r"(a[2]), "r"(a[3]), "r"(b0), "r"(b1));
}

// ============ HMMA KNN (R9 structure): approx Gram + in-register top-4,
// keys streamed through a cp.async 3-stage ring, K-chunk = 64 ===============
template<int C>
__global__ __launch_bounds__(256) void knn_mma(const __nv_bfloat16* __restrict__ XA,
                                               const __nv_bfloat16* __restrict__ XB,
                                               const float* __restrict__ sq,
                                               int* __restrict__ cand)
{
    constexpr int Ka    = 3 * C;
    constexpr int AKROW = Ka + 8;
    constexpr int BROW  = 72;           // 64 + 8 pad
    constexpr int BSTG  = 128 * BROW;   // halves per key stage
    constexpr int NK    = Ka / 64;
    constexpr int NT    = N_ / 128;
    constexpr int NCH   = NT * NK;
    extern __shared__ __align__(16) float knnpool[];
    __nv_bfloat16* As = (__nv_bfloat16*)knnpool;
    __nv_bfloat16* Bs = (__nv_bfloat16*)((char*)knnpool + 128 * AKROW * 2);

    const int b  = blockIdx.y;
    const int q0 = blockIdx.x * 128;
    const size_t rb = (size_t)b * N_;
    const int t = threadIdx.x, wid = t >> 5, lane = t & 31;
    const int wm = wid & 1, wn = wid >> 1;
    const int gid = lane >> 2, tig = lane & 3;
    const uint32_t uA = s2u(As), uB = s2u(Bs);

    // resident query tile
    for (int idx = t; idx < 128 * (Ka / 8); idx += 256) {
        int r = idx / (Ka / 8), c8 = idx % (Ka / 8);
        uint4 v = *(const uint4*)(XA + (rb + q0 + r) * (size_t)Ka + c8 * 8);
        *(uint4*)(As + r * AKROW + c8 * 8) = v;
    }
    __syncthreads();

    const int a_r  = wm * 64 + (lane & 15);
    const int a_c8 = (lane >> 4) * 8;
    const int b_rl = wn * 32 + ((lane >> 4) << 3) + (lane & 7);
    const int b_c8 = ((lane >> 3) & 1) * 8;

    float sqq8[8];
    #pragma unroll
    for (int i = 0; i < 8; i++) {
        int mt = i >> 1, h = i & 1;
        sqq8[i] = sq[rb + q0 + wm * 64 + mt * 16 + h * 8 + gid];
    }

    float bv[8][4]; int bix[8][4];
    #pragma unroll
    for (int i = 0; i < 8; i++)
        #pragma unroll
        for (int j = 0; j < 4; j++) { bv[i][j] = -3.4e38f; bix[i][j] = 0x7fffffff; }

    // key staging: 128 rows x 64 halves = 1024 x 16B chunks; 4 per thread
    auto kissue = [&](int cc2) {
        if (cc2 < NCH) {
            int kt2 = cc2 / NK, ch2 = cc2 % NK;
            int s = cc2 % 3;
            const __nv_bfloat16* p = XB + (rb + kt2 * 128) * (size_t)Ka + ch2 * 64;
            uint32_t db = uB + 2u * (s * BSTG);
            #pragma unroll
            for (int q = 0; q < 4; q++) {
                int idx = t + q * 256;
                int r = idx >> 3, c8 = idx & 7;
                cp16(db + 2u * (r * BROW + c8 * 8),
                     p + (size_t)r * Ka + c8 * 8);
            }
        }
        CP_COMMIT();
    };

    kissue(0); kissue(1);
    int cc = 0;
    for (int kt = 0; kt < NT; kt++) {
        float acc[4][4][4];
        #pragma unroll
        for (int mt = 0; mt < 4; mt++)
            #pragma unroll
            for (int nt = 0; nt < 4; nt++)
                #pragma unroll
                for (int e = 0; e < 4; e++) acc[mt][nt][e] = 0.f;

        for (int ch = 0; ch < NK; ch++) {
            CP_WAIT1();
            __syncthreads();
            const uint32_t uBs = uB + 2u * ((cc % 3) * BSTG);
            #pragma unroll
            for (int ks = 0; ks < 64; ks += 16) {
                uint32_t af[4][4], bf[2][4];
                #pragma unroll
                for (int mt = 0; mt < 4; mt++)
                    ldmx4(af[mt], uA + 2u * ((a_r + mt * 16) * AKROW + ch * 64 + ks + a_c8));
                #pragma unroll
                for (int n2 = 0; n2 < 2; n2++)
                    ldmx4(bf[n2], uBs + 2u * ((b_rl + n2 * 16) * BROW + ks + b_c8));
                #pragma unroll
                for (int mt = 0; mt < 4; mt++)
                    #pragma unroll
                    for (int nt = 0; nt < 4; nt++)
                        mma16816(acc[mt][nt], af[mt],
                                 bf[nt >> 1][(nt & 1) * 2], bf[nt >> 1][(nt & 1) * 2 + 1]);
            }
            kissue(cc + 2);
            cc++;
        }

        // selection for this key tile (in-register, parallel across threads)
        #pragma unroll
        for (int nt = 0; nt < 4; nt++) {
            int c0 = kt * 128 + wn * 32 + nt * 8 + tig * 2;
            float sk0 = sq[rb + c0], sk1 = sq[rb + c0 + 1];
            #pragma unroll
            for (int mt = 0; mt < 4; mt++)
                #pragma unroll
                for (int e = 0; e < 4; e++) {
                    int i8 = mt * 2 + (e >> 1);
                    float d = 2.0f * acc[mt][nt][e] - sqq8[i8] - ((e & 1) ? sk1 : sk0);
                    top4_insert(d, c0 + (e & 1), bv[i8], bix[i8]);
                }
        }
    }

    // merge: 16 threads x top4 -> top8 per row
    __syncthreads();
    float* cv = knnpool;
    int*   ci = (int*)(knnpool + 128 * 64);
    #pragma unroll
    for (int i = 0; i < 8; i++) {
        int mt = i >> 1, h = i & 1;
        int rowL = wm * 64 + mt * 16 + h * 8 + gid;
        int slot = wn * 16 + tig * 4;
        #pragma unroll
        for (int j = 0; j < 4; j++) {
            cv[rowL * 64 + slot + j] = bv[i][j];
            ci[rowL * 64 + slot + j] = bix[i][j];
        }
    }
    __syncthreads();
    if (t < 128) {
        float v8[8]; int i8[8];
        #pragma unroll
        for (int r = 0; r < 8; r++) { v8[r] = -3.4e38f; i8[r] = 0x7fffffff; }
        for (int j = 0; j < 64; j++)
            topD_insert<8>(cv[t * 64 + j], ci[t * 64 + j], v8, i8);
        int* op = cand + (rb + q0 + t) * 8;
        #pragma unroll
        for (int r = 0; r < 8; r++) op[r] = i8[r];
    }
}

static inline int knnmma_smem(int C) {
    int Ka = 3 * C;
    int as = 128 * (Ka + 8) * 2;
    int bs = 3 * 128 * 72 * 2;
    int tot = as + bs, mg = 128 * 64 * 8;
    return tot > mg ? tot : mg;
}

// ---- fixup: exact fp32 distances over 8 candidates -> final top-4 --------
__global__ void fixup_k(const float* __restrict__ X, int ldx, int C,
                        const float* __restrict__ sq,
                        const int* __restrict__ cand, int* __restrict__ out)
{
    int w = blockIdx.x * 8 + (threadIdx.x >> 5);
    int lane = threadIdx.x & 31;
    if (w >= B_ * N_) return;
    size_t rb = (size_t)(w >> 11) << 11;        // N_ = 2048
    int id = 0; float d = -3.4e38f;
    if (lane < 8) {
        id = cand[w * 8 + lane];
        const float* qp = X + (size_t)w * ldx;
        const float* kp = X + (rb + id) * ldx;
        float dot = 0.f;
        for (int c = 0; c < C; c += 4) {
            float4 a = *(const float4*)(qp + c);
            float4 b2 = *(const float4*)(kp + c);
            dot += a.x * b2.x + a.y * b2.y + a.z * b2.z + a.w * b2.w;
        }
        d = 2.0f * dot - sq[w] - sq[rb + id];
    }
    float v4[4]; int i4[4];
    #pragma unroll
    for (int r = 0; r < 4; r++) { v4[r] = -3.4e38f; i4[r] = 0x7fffffff; }
    #pragma unroll
    for (int j = 0; j < 8; j++) {
        float dj = __shfl_sync(0xffffffffu, d, j);
        int   ij = __shfl_sync(0xffffffffu, id, j);
        top4_insert(dj, ij, v4, i4);
    }
    if (lane == 0) {
        int4 o = make_int4(i4[0], i4[1], i4[2], i4[3]);
        *(int4*)(out + (size_t)w * 4) = o;
    }
}

// ---------------- pack W (O x 2C) -> W' (2O x C) ----------------
__global__ void packw_k(const float* __restrict__ W, float* __restrict__ Wp, int O, int Cc)
{
    int t = blockIdx.x * blockDim.x + threadIdx.x;
    int tot = 2 * O * Cc;
    if (t >= tot) return;
    int r = t / Cc, c = t % Cc;
    Wp[t] = (r < O) ? W[r * (2*Cc) + c] : W[(r - O) * (2*Cc) + Cc + c];
}

// ------- split fp32 -> bf16 limbs, K-expanded by term pattern --------------
__global__ void split_k(const float* __restrict__ src, int lds, int C,
                        unsigned patbits, int nT, int Kpad, int R,
                        __nv_bfloat16* __restrict__ dst)
{
    int t = blockIdx.x * blockDim.x + threadIdx.x;
    int tot = R * Kpad;
    if (t >= tot) return;
    int col = t % Kpad;
    int r   = t / Kpad;
    float v = 0.f;
    if (col < nT * C) {
        int tb = col / C, c = col - tb * C;
        float x = src[(size_t)r * lds + c];
        float h = __bfloat162float(__float2bfloat16(x));
        float m = x - h;
        int p = (patbits >> (3 * tb)) & 7;
        v = (p == 0) ? h : m;
    }
    dst[t] = __float2bfloat16(v);
}

// ---------------- SIMT NT SGEMM (precision-critical layers) ----------------
__device__ __forceinline__ void g2s_tile(float* S, const float* M, int ld,
                                         int r0, int k0, int K, int cq, int li)
{
    const float* rp = M + (size_t)(r0 + li) * ld;
    int c = k0 + cq * 4;
    float x, y, z, w;
    if (c + 3 < K && (((uintptr_t)(rp + c) & 15u) == 0)) {
        float4 v = *(const float4*)(rp + c);
        x = v.x; y = v.y; z = v.z; w = v.w;
    } else {
        x = (c + 0 < K) ? rp[c + 0] : 0.f;
        y = (c + 1 < K) ? rp[c + 1] : 0.f;
        z = (c + 2 < K) ? rp[c + 2] : 0.f;
        w = (c + 3 < K) ? rp[c + 3] : 0.f;
    }
    S[(cq*4+0)*68 + li] = x;
    S[(cq*4+1)*68 + li] = y;
    S[(cq*4+2)*68 + li] = z;
    S[(cq*4+3)*68 + li] = w;
}

__global__ __launch_bounds__(256) void gemm_nt(int K,
    const float* __restrict__ A,  int lda, size_t sA,
    const float* __restrict__ Bm, int ldb, size_t sB,
    float* __restrict__ Cm,       int ldc, size_t sC)
{
    __shared__ __align__(16) float As[16 * 68];
    __shared__ __align__(16) float Bs[16 * 68];
    const int bz = blockIdx.z;
    A  += (size_t)bz * sA;
    Bm += (size_t)bz * sB;
    Cm += (size_t)bz * sC;
    const int i0 = blockIdx.y * 64, j0 = blockIdx.x * 64;
    const int t  = threadIdx.x;
    const int tx = t & 15, ty = t >> 4;
    const int cq = t & 3,  li = t >> 2;

    float acc[4][4];
    #pragma unroll
    for (int i = 0; i < 4; i++)
        #pragma unroll
        for (int j = 0; j < 4; j++) acc[i][j] = 0.f;

    for (int k0 = 0; k0 < K; k0 += 16) {
        g2s_tile(As, A,  lda, i0, k0, K, cq, li);
        g2s_tile(Bs, Bm, ldb, j0, k0, K, cq, li);
        __syncthreads();
        #pragma unroll
        for (int c = 0; c < 16; c++) {
            float4 a4 = *(const float4*)&As[c*68 + ty*4];
            float4 b4 = *(const float4*)&Bs[c*68 + tx*4];
            float aa[4] = {a4.x, a4.y, a4.z, a4.w};
            float bb[4] = {b4.x, b4.y, b4.z, b4.w};
            #pragma unroll
            for (int i = 0; i < 4; i++)
                #pragma unroll
                for (int j = 0; j < 4; j++)
                    acc[i][j] += aa[i] * bb[j];
        }
        __syncthreads();
    }
    #pragma unroll
    for (int r = 0; r < 4; r++) {
        float4 v = make_float4(acc[r][0], acc[r][1], acc[r][2], acc[r][3]);
        *(float4*)&Cm[(size_t)(i0 + ty*4 + r) * ldc + j0 + tx*4] = v;
    }
}

// ============== HMMA bf16 NT-GEMM, cp.async 3-stage, K-chunk 64 ===========
#define KC   64
#define KPAD 8
#define AROW (KC + KPAD)
#define GSTG (128 * AROW)
#define GSMEM (3 * GSTG * 2 * 2)

__global__ __launch_bounds__(256) void gemm_mma(int Ka,
    const __nv_bfloat16* __restrict__ A, int lda, size_t sA,
    const __nv_bfloat16* __restrict__ B, int ldb, size_t sB,
    float* __restrict__ D, int ldd, size_t sD)
{
    extern __shared__ __align__(16) __nv_bfloat16 gsm[];
    __nv_bfloat16* As = gsm;
    __nv_bfloat16* Bs = gsm + 3 * GSTG;
    const int bz = blockIdx.z;
    A += (size_t)bz * sA;
    B += (size_t)bz * sB;
    D += (size_t)bz * sD;
    const int i0 = blockIdx.y * 128;
    const int j0 = blockIdx.x * 128;
    const int t = threadIdx.x, wid = t >> 5, lane = t & 31;
    const int wm = wid & 1, wn = wid >> 1;
    const int gid = lane >> 2, tig = lane & 3;

    const uint32_t uA = s2u(As), uB = s2u(Bs);

    const int a_r  = wm * 64 + (lane & 15);
    const int a_c8 = (lane >> 4) * 8;
    const int b_r  = wn * 32 + ((lane >> 4) << 3) + (lane & 7);
    const int b_c8 = ((lane >> 3) & 1) * 8;

    float acc[4][4][4];
    #pragma unroll
    for (int mt = 0; mt < 4; mt++)
        #pragma unroll
        for (int nt = 0; nt < 4; nt++)
            #pragma unroll
            for (int e = 0; e < 4; e++) acc[mt][nt][e] = 0.f;

    const int nk = Ka / KC;

    // staging: 128 rows x 64 halves per operand = 1024 x 16B; 4/thread each
    auto issue = [&](int k2) {
        if (k2 < nk) {
            int s = k2 % 3;
            const __nv_bfloat16* Ag = A + (size_t)i0 * lda + k2 * KC;
            const __nv_bfloat16* Bg = B + (size_t)j0 * ldb + k2 * KC;
            uint32_t da = uA + 2u * (s * GSTG);
            uint32_t db = uB + 2u * (s * GSTG);
            #pragma unroll
            for (int q = 0; q < 4; q++) {
                int idx = t + q * 256;
                int r = idx >> 3, c8 = idx & 7;
                cp16(da + 2u * (r * AROW + c8 * 8), Ag + (size_t)r * lda + c8 * 8);
                cp16(db + 2u * (r * AROW + c8 * 8), Bg + (size_t)r * ldb + c8 * 8);
            }
        }
        CP_COMMIT();
    };

    issue(0); issue(1);
    for (int k = 0; k < nk; k++) {
        CP_WAIT1();
        __syncthreads();
        const int s = k % 3;
        const uint32_t uAs = uA + 2u * (s * GSTG);
        const uint32_t uBs = uB + 2u * (s * GSTG);
        #pragma unroll
        for (int ks = 0; ks < KC; ks += 16) {
            uint32_t af[4][4], bf[2][4];
            #pragma unroll
            for (int mt = 0; mt < 4; mt++)
                ldmx4(af[mt], uAs + 2u * ((a_r + mt * 16) * AROW + ks + a_c8));
            #pragma unroll
            for (int n2 = 0; n2 < 2; n2++)
                ldmx4(bf[n2], uBs + 2u * ((b_r + n2 * 16) * AROW + ks + b_c8));
            #pragma unroll
            for (int mt = 0; mt < 4; mt++)
                #pragma unroll
                for (int nt = 0; nt < 4; nt++)
                    mma16816(acc[mt][nt], af[mt],
                             bf[nt >> 1][(nt & 1) * 2], bf[nt >> 1][(nt & 1) * 2 + 1]);
        }
        issue(k + 2);
    }

    #pragma unroll
    for (int mt = 0; mt < 4; mt++) {
        int r = i0 + wm * 64 + mt * 16 + gid;
        #pragma unroll
        for (int nt = 0; nt < 4; nt++) {
            int c = j0 + wn * 32 + nt * 8 + tig * 2;
            *(float2*)&D[(size_t)r * ldd + c]       = make_float2(acc[mt][nt][0], acc[mt][nt][1]);
            *(float2*)&D[(size_t)(r + 8) * ldd + c] = make_float2(acc[mt][nt][2], acc[mt][nt][3]);
        }
    }
}

// ---------------- gather + relu + max-over-k epilogue ---------------------
__global__ void edge_epi_k(const float* __restrict__ Z, const int* __restrict__ idx,
                           float* __restrict__ Fo, int O)
{
    const int b = blockIdx.y, n = blockIdx.x;
    const size_t rb = (size_t)b * N_;
    int4 id = *(const int4*)(idx + (rb + n) * 4);
    const size_t w = (size_t)(2 * O);
    const float* zb = Z + rb * w;
    const float* z0 = zb + (size_t)id.x * w;
    const float* z1 = zb + (size_t)id.y * w;
    const float* z2 = zb + (size_t)id.z * w;
    const float* z3 = zb + (size_t)id.w * w;
    const float* zc = zb + (size_t)n * w + O;
    float* fo = Fo + (rb + n) * LDF;
    for (int o = threadIdx.x; o < O; o += blockDim.x) {
        float m = fmaxf(fmaxf(z0[o], z1[o]), fmaxf(z2[o], z3[o]));
        fo[o] = fmaxf(m + zc[o], 0.f);
    }
}

// ---------------- orchestration ----------------
extern "C" void kernel_launch(void* const* d_in, const int* in_sizes, int n_in,
                              void* d_out, int out_size)
{
    const float* x  = (const float*)d_in[0];
    const float* W1 = (const float*)d_in[1];
    const float* W2 = (const float*)d_in[2];
    const float* W3 = (const float*)d_in[3];
    const float* W4 = (const float*)d_in[4];
    const float* W5 = (const float*)d_in[5];
    float* out = (float*)d_out;

    void* p;
    cudaGetSymbolAddress(&p, g_X0);  float* X0 = (float*)p;
    cudaGetSymbolAddress(&p, g_F );  float* F  = (float*)p;
    cudaGetSymbolAddress(&p, g_Z );  float* Z  = (float*)p;
    cudaGetSymbolAddress(&p, g_SQ);  float* SQ = (float*)p;
    cudaGetSymbolAddress(&p, g_ID);  int*   ID = (int*)p;
    cudaGetSymbolAddress(&p, g_C8);  int*   C8 = (int*)p;
    cudaGetSymbolAddress(&p, g_WPf); float* WPf = (float*)p;
    cudaGetSymbolAddress(&p, g_Xb);  __nv_bfloat16* Xb  = (__nv_bfloat16*)p;
    cudaGetSymbolAddress(&p, g_Xb2); __nv_bfloat16* Xb2 = (__nv_bfloat16*)p;
    cudaGetSymbolAddress(&p, g_Wb);  __nv_bfloat16* Wb  = (__nv_bfloat16*)p;

    cudaFuncSetAttribute(knn_mma<64>,
        cudaFuncAttributeMaxDynamicSharedMemorySize, knnmma_smem(64));
    cudaFuncSetAttribute(knn_mma<128>,
        cudaFuncAttributeMaxDynamicSharedMemorySize, knnmma_smem(128));
    cudaFuncSetAttribute(gemm_mma,
        cudaFuncAttributeMaxDynamicSharedMemorySize, GSMEM);

    // split patterns (3-term, 2-limb): A gets {h,h,l}, B gets {h,l,h}
    const unsigned PAT_A = 0u | (0u << 3) | (1u << 6);
    const unsigned PAT_B = 0u | (1u << 3) | (0u << 6);

    tr_x0_k<<<(B_*3*N_ + 255)/256, 256>>>(x, X0);

    // HMMA-based knn for C in {64,128}: split -> approx top8 -> exact fixup
    auto knn_tc = [&](const float* Xin, int C) {
        int Kp = 3 * C;
        sqnorm_k<<<(B_*N_*32)/256, 256>>>(Xin, LDF, C, SQ);
        split_k<<<(B_*N_*Kp + 255)/256, 256>>>(Xin, LDF, C, PAT_A, 3, Kp, B_*N_, Xb);
        split_k<<<(B_*N_*Kp + 255)/256, 256>>>(Xin, LDF, C, PAT_B, 3, Kp, B_*N_, Xb2);
        dim3 kg(N_/128, B_);
        if (C == 64)
            knn_mma<64> <<<kg, 256, knnmma_smem(64) >>>(Xb, Xb2, SQ, C8);
        else
            knn_mma<128><<<kg, 256, knnmma_smem(128)>>>(Xb, Xb2, SQ, C8);
        fixup_k<<<(B_*N_)/8, 256>>>(Xin, LDF, C, SQ, C8, ID);
    };

    // ---- layer 1: fp32 knn (C=3) + SIMT z-GEMM
    {
        sqnorm_k<<<(B_*N_*32)/256, 256>>>(X0, 3, 3, SQ);
        knn3_kernel<<<dim3(N_/64, B_), 256>>>(X0, SQ, ID);
        packw_k<<<(2*64*3 + 255)/256, 256>>>(W1, WPf, 64, 3);
        dim3 gg(128/64, (B_*N_)/64, 1);
        gemm_nt<<<gg, 256>>>(3, X0, 3, (size_t)0, WPf, 3, (size_t)0,
                             Z, 128, (size_t)0);
        edge_epi_k<<<dim3(N_, B_), 64>>>(Z, ID, F + 0, 64);
    }

    // ---- layers 2-3: HMMA knn + SIMT fp32 z-GEMM (z feeds next knn)
    auto layer23 = [&](const float* Xin, int C, int O, const float* W, float* Fout) {
        knn_tc(Xin, C);
        packw_k<<<(2*O*C + 255)/256, 256>>>(W, WPf, O, C);
        dim3 gg((2*O)/64, (B_*N_)/64, 1);
        gemm_nt<<<gg, 256>>>(C, Xin, LDF, (size_t)0, WPf, C, (size_t)0,
                             Z, 2*O, (size_t)0);
        edge_epi_k<<<dim3(N_, B_), O>>>(Z, ID, Fout, O);
    };
    layer23(F + 0,  64, 64,  W2, F + 64);    // x2 -> F[:, 64:128]
    layer23(F + 64, 64, 128, W3, F + 128);   // x3 -> F[:, 128:256]

    // ---- layer 4: HMMA knn + HMMA z-GEMM (Xb = PAT_A split of F+128)
    {
        const int C = 128, O = 256, Kp = 3 * C;       // 384
        knn_tc(F + 128, C);
        packw_k<<<(2*O*C + 255)/256, 256>>>(W4, WPf, O, C);
        split_k<<<(2*O*Kp + 255)/256, 256>>>(WPf, C, C, PAT_B, 3, Kp, 2*O, Wb);
        dim3 gg((2*O)/128, (B_*N_)/128, 1);
        gemm_mma<<<gg, 256, GSMEM>>>(Kp, Xb, Kp, (size_t)0, Wb, Kp, (size_t)0,
                                     Z, 2*O, (size_t)0);
        edge_epi_k<<<dim3(N_, B_), O>>>(Z, ID, F + 256, O);
    }

    // ---- final: out[b][o][n] = W5 · concat-features, HMMA
    {
        const int C = 512, Kp = 3 * C;                // 1536
        split_k<<<(512*Kp + 255)/256, 256>>>(W5, C, C, PAT_B, 3, Kp, 512, Wb);
        split_k<<<(B_*N_*Kp + 255)/256, 256>>>(F, LDF, C, PAT_A, 3, Kp, B_*N_, Xb);
        dim3 fg(N_/128, 512/128, B_);
        gemm_mma<<<fg, 256, GSMEM>>>(Kp,
                                     Wb, Kp, (size_t)0,
                                     Xb, Kp, (size_t)N_ * Kp,
                                     out, N_, (size_t)512 * N_);
    }
}

// round 12
// speedup vs baseline: 1.1300x; 1.0167x over previous
#include <cuda_runtime.h>
#include <cuda_bf16.h>
#include <cstdint>
#include <cstddef>

#define B_  8
#define N_  2048
#define LDF 512

// ---------------- scratch (device globals: allocation-free) ----------------
__device__ __align__(16) float g_X0[B_ * N_ * 3];
__device__ __align__(16) float g_F [B_ * N_ * LDF];      // concat features [b][n][512]
__device__ __align__(16) float g_Z [B_ * N_ * LDF];      // z = W' x, rows [m][2O]
__device__ __align__(16) float g_SQ[B_ * N_];
__device__ __align__(16) int   g_ID[B_ * N_ * 4];
__device__ __align__(16) int   g_C8[B_ * N_ * 8];        // knn top-8 candidates
__device__ __align__(16) float g_WPf[512 * 128];         // packed W' fp32 (2O x C)
__device__ __align__(16) __nv_bfloat16 g_Xb[B_ * N_ * 1536]; // expanded split (gemm A)
__device__ __align__(16) __nv_bfloat16 g_Xc[B_ * N_ * 256];  // compact [h|l] (knn)
__device__ __align__(16) __nv_bfloat16 g_Wb[512 * 1536];     // expanded split weights

__device__ __forceinline__ uint32_t s2u(const void* p) {
    uint32_t a;
    asm("{ .reg .u64 t; cvta.to.shared.u64 t, %1; cvt.u32.u64 %0, t; }" : "=r"(a) : "l"(p));
    return a;
}
// ---- cp.async helpers ----
__device__ __forceinline__ void cp16(uint32_t dst, const void* src) {
    asm volatile("cp.async.cg.shared.global [%0], [%1], 16;" :: "r"(dst), "l"(src));
}
#define CP_COMMIT() asm volatile("cp.async.commit_group;" ::: "memory")
#define CP_WAIT1()  asm volatile("cp.async.wait_group 1;" ::: "memory")

// ---------------- transpose x (B,3,N) -> X0 [b][n][3] ----------------
__global__ void tr_x0_k(const float* __restrict__ x, float* __restrict__ X0)
{
    int t = blockIdx.x * blockDim.x + threadIdx.x;
    const int tot = B_ * 3 * N_;
    if (t >= tot) return;
    int b = t / (3 * N_);
    int r = t % (3 * N_);
    int c = r / N_;
    int n = r % N_;
    X0[((size_t)b * N_ + n) * 3 + c] = x[t];
}

// ---------------- squared norms ----------------
__global__ void sqnorm_k(const float* __restrict__ X, int ldx, int C,
                         float* __restrict__ sq)
{
    int w    = (blockIdx.x * blockDim.x + threadIdx.x) >> 5;
    int lane = threadIdx.x & 31;
    if (w >= B_ * N_) return;
    const float* r = X + (size_t)w * ldx;
    float s = 0.f;
    for (int c = lane; c < C; c += 32) { float v = r[c]; s += v * v; }
    #pragma unroll
    for (int o = 16; o; o >>= 1) s += __shfl_xor_sync(0xffffffffu, s, o);
    if (lane == 0) sq[w] = s;
}

// ---------------- top-D insertion (value desc, tie: lower index) ----------
template<int D>
__device__ __forceinline__ void topD_insert(float d, int id, float (&v)[D], int (&ix)[D])
{
    if (d > v[D-1] || (d == v[D-1] && id < ix[D-1])) {
        v[D-1] = d; ix[D-1] = id;
        #pragma unroll
        for (int s = D-1; s > 0; s--) {
            if (v[s] > v[s-1] || (v[s] == v[s-1] && ix[s] < ix[s-1])) {
                float tv = v[s]; v[s] = v[s-1]; v[s-1] = tv;
                int   ti = ix[s]; ix[s] = ix[s-1]; ix[s-1] = ti;
            } else break;
        }
    }
}
__device__ __forceinline__ void top4_insert(float d, int id, float (&v)[4], int (&ix)[4])
{ topD_insert<4>(d, id, v, ix); }

// ---------------- fused KNN for C=3 (fp32-exact) --------------------------
__global__ __launch_bounds__(256) void knn3_kernel(const float* __restrict__ X,
                                                   const float* __restrict__ sq,
                                                   int* __restrict__ out_idx)
{
    constexpr int C = 3, QROW = 68;
    __shared__ __align__(16) float pool[64 * 64 * 2];
    float* Qs = pool;
    float* Ks = pool + C * QROW;

    const int b  = blockIdx.y;
    const int q0 = blockIdx.x * 64;
    const int t  = threadIdx.x;
    const int tx = t & 15, ty = t >> 4;
    const size_t rb = (size_t)b * N_;

    for (int f = t; f < 64 * C; f += 256) {
        int c = f % C, m = f / C;
        Qs[c*QROW + m] = X[(rb + q0 + m) * 3 + c];
    }

    float sqq[4];
    #pragma unroll
    for (int i = 0; i < 4; i++) sqq[i] = sq[rb + q0 + ty*4 + i];

    float bv[4][4]; int bix[4][4];
    #pragma unroll
    for (int i = 0; i < 4; i++)
        #pragma unroll
        for (int j = 0; j < 4; j++) { bv[i][j] = -3.4e38f; bix[i][j] = 0x7fffffff; }

    for (int kb = 0; kb < N_; kb += 64) {
        float acc[4][4];
        #pragma unroll
        for (int i = 0; i < 4; i++)
            #pragma unroll
            for (int j = 0; j < 4; j++) acc[i][j] = 0.f;

        __syncthreads();
        for (int f = t; f < 64 * C; f += 256) {
            int c = f % C, m = f / C;
            Ks[c*QROW + m] = X[(rb + kb + m) * 3 + c];
        }
        __syncthreads();
        #pragma unroll
        for (int c = 0; c < C; c++) {
            float4 q4 = *(const float4*)&Qs[c*QROW + ty*4];
            float4 k4 = *(const float4*)&Ks[c*QROW + tx*4];
            float qa[4] = {q4.x, q4.y, q4.z, q4.w};
            float ka[4] = {k4.x, k4.y, k4.z, k4.w};
            #pragma unroll
            for (int i = 0; i < 4; i++)
                #pragma unroll
                for (int j = 0; j < 4; j++)
                    acc[i][j] += qa[i] * ka[j];
        }

        float sqk[4];
        #pragma unroll
        for (int j = 0; j < 4; j++) sqk[j] = sq[rb + kb + tx*4 + j];

        #pragma unroll
        for (int i = 0; i < 4; i++)
            #pragma unroll
            for (int j = 0; j < 4; j++) {
                float d = 2.0f * acc[i][j] - sqq[i] - sqk[j];
                top4_insert(d, kb + tx*4 + j, bv[i], bix[i]);
            }
    }

    __syncthreads();
    float* cv = pool;
    int*   ci = (int*)(pool + 64 * 64);
    #pragma unroll
    for (int qi = 0; qi < 4; qi++) {
        int base = (ty*4 + qi) * 64 + tx * 4;
        #pragma unroll
        for (int r = 0; r < 4; r++) { cv[base + r] = bv[qi][r]; ci[base + r] = bix[qi][r]; }
    }
    __syncthreads();
    if (t < 64) {
        float v4[4]; int i4[4];
        #pragma unroll
        for (int r = 0; r < 4; r++) { v4[r] = -3.4e38f; i4[r] = 0x7fffffff; }
        for (int j = 0; j < 64; j++)
            top4_insert(cv[t*64 + j], ci[t*64 + j], v4, i4);
        int* op = out_idx + (rb + q0 + t) * 4;
        op[0] = i4[0]; op[1] = i4[1]; op[2] = i4[2]; op[3] = i4[3];
    }
}

// ---------------- HMMA helpers ----------------
__device__ __forceinline__ void ldmx4(uint32_t (&r)[4], uint32_t addr)
{
    asm volatile("ldmatrix.sync.aligned.m8n8.x4.shared.b16 {%0,%1,%2,%3}, [%4];"
                 : "=r"(r[0]), "=r"(r[1]), "=r"(r[2]), "=r"(r[3]) : "r"(addr));
}
__device__ __forceinline__ void mma16816(float (&d)[4], const uint32_t (&a)[4],
                                         uint32_t b0, uint32_t b1)
{
    asm volatile(
        "mma.sync.aligned.m16n8k16.row.col.f32.bf16.bf16.f32 "
        "{%0,%1,%2,%3}, {%4,%5,%6,%7}, {%8,%9}, {%0,%1,%2,%3};"
        : "+f"(d[0]), "+f"(d[1]), "+f"(d[2]), "+f"(d[3])
        : "r"(a[0]), "r"(a[1]), "r"(a[2]), "r"(a[3]), "r"(b0), "r"(b1));
}

// ------- compact split: fp32 -> [h | l] bf16 limbs (2C cols) --------------
__global__ void split_hl(const float* __restrict__ src, int lds, int C, int R,
                         __nv_bfloat16* __restrict__ dst)
{
    int t = blockIdx.x * blockDim.x + threadIdx.x;
    int Kc = 2 * C;
    int tot = R * Kc;
    if (t >= tot) return;
    int col = t % Kc;
    int r   = t / Kc;
    int c   = (col < C) ? col : col - C;
    float x = src[(size_t)r * lds + c];
    float h = __bfloat162float(__float2bfloat16(x));
    float v = (col < C) ? h : (x - h);
    dst[t] = __float2bfloat16(v);
}

// ===== HMMA KNN on compact [h|l]: 3-term expansion via chunk addressing ===
// A expanded chunks = [h,h,l]; B expanded = [h,l,h]  (same arithmetic order
// as the explicit expanded buffers -> bit-identical accumulation).
// Whole compact key tiles streamed via cp.async; NBUF=3 (C=64) / 2 (C=128).
template<int C>
__global__ __launch_bounds__(256) void knn_mma2(const __nv_bfloat16* __restrict__ XC,
                                                const float* __restrict__ sq,
                                                int* __restrict__ cand)
{
    constexpr int Kc    = 2 * C;
    constexpr int AKROW = Kc + 8;          // halves; 2*AKROW mod 128B == 16B
    constexpr int BSTG  = 128 * AKROW;
    constexpr int NEXP  = (3 * C) / 64;    // expanded 64-chunks
    constexpr int NBUF  = (C == 64) ? 3 : 2;
    constexpr int NT    = N_ / 128;
    constexpr int NCP   = Kc / 16;         // cp16 per thread per tile
    extern __shared__ __align__(16) float knnpool[];
    __nv_bfloat16* As = (__nv_bfloat16*)knnpool;
    __nv_bfloat16* Bs = As + BSTG;

    // expanded-chunk -> compact offset (halves)
    int AOFF[NEXP], BOFF[NEXP];
    if constexpr (C == 64) {
        AOFF[0] = 0;  AOFF[1] = 0;   AOFF[2] = 64;
        BOFF[0] = 0;  BOFF[1] = 64;  BOFF[2] = 0;
    } else {
        AOFF[0] = 0;   AOFF[1] = 64;  AOFF[2] = 0;   AOFF[3] = 64;  AOFF[4] = 128; AOFF[5] = 192;
        BOFF[0] = 0;   BOFF[1] = 64;  BOFF[2] = 128; BOFF[3] = 192; BOFF[4] = 0;   BOFF[5] = 64;
    }

    const int b  = blockIdx.y;
    const int q0 = blockIdx.x * 128;
    const size_t rb = (size_t)b * N_;
    const int t = threadIdx.x, wid = t >> 5, lane = t & 31;
    const int wm = wid & 1, wn = wid >> 1;
    const int gid = lane >> 2, tig = lane & 3;
    const uint32_t uA = s2u(As), uB = s2u(Bs);

    // resident compact query tile
    for (int idx = t; idx < 128 * (Kc / 8); idx += 256) {
        int r = idx / (Kc / 8), c8 = idx % (Kc / 8);
        uint4 v = *(const uint4*)(XC + (rb + q0 + r) * (size_t)Kc + c8 * 8);
        *(uint4*)(As + r * AKROW + c8 * 8) = v;
    }
    __syncthreads();

    const int a_r  = wm * 64 + (lane & 15);
    const int a_c8 = (lane >> 4) * 8;
    const int b_rl = wn * 32 + ((lane >> 4) << 3) + (lane & 7);
    const int b_c8 = ((lane >> 3) & 1) * 8;

    float sqq8[8];
    #pragma unroll
    for (int i = 0; i < 8; i++) {
        int mt = i >> 1, h = i & 1;
        sqq8[i] = sq[rb + q0 + wm * 64 + mt * 16 + h * 8 + gid];
    }

    float bv[8][4]; int bix[8][4];
    #pragma unroll
    for (int i = 0; i < 8; i++)
        #pragma unroll
        for (int j = 0; j < 4; j++) { bv[i][j] = -3.4e38f; bix[i][j] = 0x7fffffff; }

    auto kissue = [&](int kt2) {
        if (kt2 < NT) {
            int s = kt2 % NBUF;
            const __nv_bfloat16* p = XC + (rb + kt2 * 128) * (size_t)Kc;
            uint32_t db = uB + 2u * (s * BSTG);
            #pragma unroll
            for (int q = 0; q < NCP; q++) {
                int idx = t + q * 256;
                int r = idx / (Kc / 8), c8 = idx % (Kc / 8);
                cp16(db + 2u * (r * AKROW + c8 * 8),
                     p + (size_t)r * Kc + c8 * 8);
            }
        }
        CP_COMMIT();
    };

    kissue(0); kissue(1);
    for (int kt = 0; kt < NT; kt++) {
        CP_WAIT1();
        __syncthreads();
        const uint32_t uBs = uB + 2u * ((kt % NBUF) * BSTG);

        float acc[4][4][4];
        #pragma unroll
        for (int mt = 0; mt < 4; mt++)
            #pragma unroll
            for (int nt = 0; nt < 4; nt++)
                #pragma unroll
                for (int e = 0; e < 4; e++) acc[mt][nt][e] = 0.f;

        #pragma unroll
        for (int i = 0; i < NEXP; i++) {
            #pragma unroll
            for (int ks = 0; ks < 64; ks += 16) {
                uint32_t af[4][4], bf[2][4];
                #pragma unroll
                for (int mt = 0; mt < 4; mt++)
                    ldmx4(af[mt], uA + 2u * ((a_r + mt * 16) * AKROW + AOFF[i] + ks + a_c8));
                #pragma unroll
                for (int n2 = 0; n2 < 2; n2++)
                    ldmx4(bf[n2], uBs + 2u * ((b_rl + n2 * 16) * AKROW + BOFF[i] + ks + b_c8));
                #pragma unroll
                for (int mt = 0; mt < 4; mt++)
                    #pragma unroll
                    for (int nt = 0; nt < 4; nt++)
                        mma16816(acc[mt][nt], af[mt],
                                 bf[nt >> 1][(nt & 1) * 2], bf[nt >> 1][(nt & 1) * 2 + 1]);
            }
        }
        if constexpr (NBUF == 2) __syncthreads();   // all warps done reading buf
        kissue(kt + 2);

        // selection for this key tile (in-register, parallel)
        #pragma unroll
        for (int nt = 0; nt < 4; nt++) {
            int c0 = kt * 128 + wn * 32 + nt * 8 + tig * 2;
            float sk0 = sq[rb + c0], sk1 = sq[rb + c0 + 1];
            #pragma unroll
            for (int mt = 0; mt < 4; mt++)
                #pragma unroll
                for (int e = 0; e < 4; e++) {
                    int i8 = mt * 2 + (e >> 1);
                    float d = 2.0f * acc[mt][nt][e] - sqq8[i8] - ((e & 1) ? sk1 : sk0);
                    top4_insert(d, c0 + (e & 1), bv[i8], bix[i8]);
                }
        }
    }

    // merge: 16 threads x top4 -> top8 per row
    __syncthreads();
    float* cv = knnpool;
    int*   ci = (int*)(knnpool + 128 * 64);
    #pragma unroll
    for (int i = 0; i < 8; i++) {
        int mt = i >> 1, h = i & 1;
        int rowL = wm * 64 + mt * 16 + h * 8 + gid;
        int slot = wn * 16 + tig * 4;
        #pragma unroll
        for (int j = 0; j < 4; j++) {
            cv[rowL * 64 + slot + j] = bv[i][j];
            ci[rowL * 64 + slot + j] = bix[i][j];
        }
    }
    __syncthreads();
    if (t < 128) {
        float v8[8]; int i8[8];
        #pragma unroll
        for (int r = 0; r < 8; r++) { v8[r] = -3.4e38f; i8[r] = 0x7fffffff; }
        for (int j = 0; j < 64; j++)
            topD_insert<8>(cv[t * 64 + j], ci[t * 64 + j], v8, i8);
        int* op = cand + (rb + q0 + t) * 8;
        #pragma unroll
        for (int r = 0; r < 8; r++) op[r] = i8[r];
    }
}

static inline int knn2_smem(int C) {
    int Kc = 2 * C, row = Kc + 8;
    int nbuf = (C == 64) ? 3 : 2;
    int tot = (1 + nbuf) * 128 * row * 2;
    int mg = 128 * 64 * 8;
    return tot > mg ? tot : mg;
}

// ---- fixup: exact fp32 distances over 8 candidates -> final top-4 --------
__global__ void fixup_k(const float* __restrict__ X, int ldx, int C,
                        const float* __restrict__ sq,
                        const int* __restrict__ cand, int* __restrict__ out)
{
    int w = blockIdx.x * 8 + (threadIdx.x >> 5);
    int lane = threadIdx.x & 31;
    if (w >= B_ * N_) return;
    size_t rb = (size_t)(w >> 11) << 11;        // N_ = 2048
    int id = 0; float d = -3.4e38f;
    if (lane < 8) {
        id = cand[w * 8 + lane];
        const float* qp = X + (size_t)w * ldx;
        const float* kp = X + (rb + id) * ldx;
        float dot = 0.f;
        for (int c = 0; c < C; c += 4) {
            float4 a = *(const float4*)(qp + c);
            float4 b2 = *(const float4*)(kp + c);
            dot += a.x * b2.x + a.y * b2.y + a.z * b2.z + a.w * b2.w;
        }
        d = 2.0f * dot - sq[w] - sq[rb + id];
    }
    float v4[4]; int i4[4];
    #pragma unroll
    for (int r = 0; r < 4; r++) { v4[r] = -3.4e38f; i4[r] = 0x7fffffff; }
    #pragma unroll
    for (int j = 0; j < 8; j++) {
        float dj = __shfl_sync(0xffffffffu, d, j);
        int   ij = __shfl_sync(0xffffffffu, id, j);
        top4_insert(dj, ij, v4, i4);
    }
    if (lane == 0) {
        int4 o = make_int4(i4[0], i4[1], i4[2], i4[3]);
        *(int4*)(out + (size_t)w * 4) = o;
    }
}

// ---------------- pack W (O x 2C) -> W' (2O x C) ----------------
__global__ void packw_k(const float* __restrict__ W, float* __restrict__ Wp, int O, int Cc)
{
    int t = blockIdx.x * blockDim.x + threadIdx.x;
    int tot = 2 * O * Cc;
    if (t >= tot) return;
    int r = t / Cc, c = t % Cc;
    Wp[t] = (r < O) ? W[r * (2*Cc) + c] : W[(r - O) * (2*Cc) + Cc + c];
}

// ------- split fp32 -> bf16 limbs, K-expanded by term pattern --------------
__global__ void split_k(const float* __restrict__ src, int lds, int C,
                        unsigned patbits, int nT, int Kpad, int R,
                        __nv_bfloat16* __restrict__ dst)
{
    int t = blockIdx.x * blockDim.x + threadIdx.x;
    int tot = R * Kpad;
    if (t >= tot) return;
    int col = t % Kpad;
    int r   = t / Kpad;
    float v = 0.f;
    if (col < nT * C) {
        int tb = col / C, c = col - tb * C;
        float x = src[(size_t)r * lds + c];
        float h = __bfloat162float(__float2bfloat16(x));
        float m = x - h;
        int p = (patbits >> (3 * tb)) & 7;
        v = (p == 0) ? h : m;
    }
    dst[t] = __float2bfloat16(v);
}

// ---------------- SIMT NT SGEMM (precision-critical layers) ----------------
__device__ __forceinline__ void g2s_tile(float* S, const float* M, int ld,
                                         int r0, int k0, int K, int cq, int li)
{
    const float* rp = M + (size_t)(r0 + li) * ld;
    int c = k0 + cq * 4;
    float x, y, z, w;
    if (c + 3 < K && (((uintptr_t)(rp + c) & 15u) == 0)) {
        float4 v = *(const float4*)(rp + c);
        x = v.x; y = v.y; z = v.z; w = v.w;
    } else {
        x = (c + 0 < K) ? rp[c + 0] : 0.f;
        y = (c + 1 < K) ? rp[c + 1] : 0.f;
        z = (c + 2 < K) ? rp[c + 2] : 0.f;
        w = (c + 3 < K) ? rp[c + 3] : 0.f;
    }
    S[(cq*4+0)*68 + li] = x;
    S[(cq*4+1)*68 + li] = y;
    S[(cq*4+2)*68 + li] = z;
    S[(cq*4+3)*68 + li] = w;
}

__global__ __launch_bounds__(256) void gemm_nt(int K,
    const float* __restrict__ A,  int lda, size_t sA,
    const float* __restrict__ Bm, int ldb, size_t sB,
    float* __restrict__ Cm,       int ldc, size_t sC)
{
    __shared__ __align__(16) float As[16 * 68];
    __shared__ __align__(16) float Bs[16 * 68];
    const int bz = blockIdx.z;
    A  += (size_t)bz * sA;
    Bm += (size_t)bz * sB;
    Cm += (size_t)bz * sC;
    const int i0 = blockIdx.y * 64, j0 = blockIdx.x * 64;
    const int t  = threadIdx.x;
    const int tx = t & 15, ty = t >> 4;
    const int cq = t & 3,  li = t >> 2;

    float acc[4][4];
    #pragma unroll
    for (int i = 0; i < 4; i++)
        #pragma unroll
        for (int j = 0; j < 4; j++) acc[i][j] = 0.f;

    for (int k0 = 0; k0 < K; k0 += 16) {
        g2s_tile(As, A,  lda, i0, k0, K, cq, li);
        g2s_tile(Bs, Bm, ldb, j0, k0, K, cq, li);
        __syncthreads();
        #pragma unroll
        for (int c = 0; c < 16; c++) {
            float4 a4 = *(const float4*)&As[c*68 + ty*4];
            float4 b4 = *(const float4*)&Bs[c*68 + tx*4];
            float aa[4] = {a4.x, a4.y, a4.z, a4.w};
            float bb[4] = {b4.x, b4.y, b4.z, b4.w};
            #pragma unroll
            for (int i = 0; i < 4; i++)
                #pragma unroll
                for (int j = 0; j < 4; j++)
                    acc[i][j] += aa[i] * bb[j];
        }
        __syncthreads();
    }
    #pragma unroll
    for (int r = 0; r < 4; r++) {
        float4 v = make_float4(acc[r][0], acc[r][1], acc[r][2], acc[r][3]);
        *(float4*)&Cm[(size_t)(i0 + ty*4 + r) * ldc + j0 + tx*4] = v;
    }
}

// ============== HMMA bf16 NT-GEMM, cp.async 3-stage, K-chunk 64 ===========
#define KC   64
#define KPAD 8
#define AROW (KC + KPAD)
#define GSTG (128 * AROW)
#define GSMEM (3 * GSTG * 2 * 2)

__global__ __launch_bounds__(256) void gemm_mma(int Ka,
    const __nv_bfloat16* __restrict__ A, int lda, size_t sA,
    const __nv_bfloat16* __restrict__ B, int ldb, size_t sB,
    float* __restrict__ D, int ldd, size_t sD)
{
    extern __shared__ __align__(16) __nv_bfloat16 gsm[];
    __nv_bfloat16* As = gsm;
    __nv_bfloat16* Bs = gsm + 3 * GSTG;
    const int bz = blockIdx.z;
    A += (size_t)bz * sA;
    B += (size_t)bz * sB;
    D += (size_t)bz * sD;
    const int i0 = blockIdx.y * 128;
    const int j0 = blockIdx.x * 128;
    const int t = threadIdx.x, wid = t >> 5, lane = t & 31;
    const int wm = wid & 1, wn = wid >> 1;
    const int gid = lane >> 2, tig = lane & 3;

    const uint32_t uA = s2u(As), uB = s2u(Bs);

    const int a_r  = wm * 64 + (lane & 15);
    const int a_c8 = (lane >> 4) * 8;
    const int b_r  = wn * 32 + ((lane >> 4) << 3) + (lane & 7);
    const int b_c8 = ((lane >> 3) & 1) * 8;

    float acc[4][4][4];
    #pragma unroll
    for (int mt = 0; mt < 4; mt++)
        #pragma unroll
        for (int nt = 0; nt < 4; nt++)
            #pragma unroll
            for (int e = 0; e < 4; e++) acc[mt][nt][e] = 0.f;

    const int nk = Ka / KC;

    auto issue = [&](int k2) {
        if (k2 < nk) {
            int s = k2 % 3;
            const __nv_bfloat16* Ag = A + (size_t)i0 * lda + k2 * KC;
            const __nv_bfloat16* Bg = B + (size_t)j0 * ldb + k2 * KC;
            uint32_t da = uA + 2u * (s * GSTG);
            uint32_t db = uB + 2u * (s * GSTG);
            #pragma unroll
            for (int q = 0; q < 4; q++) {
                int idx = t + q * 256;
                int r = idx >> 3, c8 = idx & 7;
                cp16(da + 2u * (r * AROW + c8 * 8), Ag + (size_t)r * lda + c8 * 8);
                cp16(db + 2u * (r * AROW + c8 * 8), Bg + (size_t)r * ldb + c8 * 8);
            }
        }
        CP_COMMIT();
    };

    issue(0); issue(1);
    for (int k = 0; k < nk; k++) {
        CP_WAIT1();
        __syncthreads();
        const int s = k % 3;
        const uint32_t uAs = uA + 2u * (s * GSTG);
        const uint32_t uBs = uB + 2u * (s * GSTG);
        #pragma unroll
        for (int ks = 0; ks < KC; ks += 16) {
            uint32_t af[4][4], bf[2][4];
            #pragma unroll
            for (int mt = 0; mt < 4; mt++)
                ldmx4(af[mt], uAs + 2u * ((a_r + mt * 16) * AROW + ks + a_c8));
            #pragma unroll
            for (int n2 = 0; n2 < 2; n2++)
                ldmx4(bf[n2], uBs + 2u * ((b_r + n2 * 16) * AROW + ks + b_c8));
            #pragma unroll
            for (int mt = 0; mt < 4; mt++)
                #pragma unroll
                for (int nt = 0; nt < 4; nt++)
                    mma16816(acc[mt][nt], af[mt],
                             bf[nt >> 1][(nt & 1) * 2], bf[nt >> 1][(nt & 1) * 2 + 1]);
        }
        issue(k + 2);
    }

    #pragma unroll
    for (int mt = 0; mt < 4; mt++) {
        int r = i0 + wm * 64 + mt * 16 + gid;
        #pragma unroll
        for (int nt = 0; nt < 4; nt++) {
            int c = j0 + wn * 32 + nt * 8 + tig * 2;
            *(float2*)&D[(size_t)r * ldd + c]       = make_float2(acc[mt][nt][0], acc[mt][nt][1]);
            *(float2*)&D[(size_t)(r + 8) * ldd + c] = make_float2(acc[mt][nt][2], acc[mt][nt][3]);
        }
    }
}

// ---------------- gather + relu + max-over-k epilogue ---------------------
__global__ void edge_epi_k(const float* __restrict__ Z, const int* __restrict__ idx,
                           float* __restrict__ Fo, int O)
{
    const int b = blockIdx.y, n = blockIdx.x;
    const size_t rb = (size_t)b * N_;
    int4 id = *(const int4*)(idx + (rb + n) * 4);
    const size_t w = (size_t)(2 * O);
    const float* zb = Z + rb * w;
    const float* z0 = zb + (size_t)id.x * w;
    const float* z1 = zb + (size_t)id.y * w;
    const float* z2 = zb + (size_t)id.z * w;
    const float* z3 = zb + (size_t)id.w * w;
    const float* zc = zb + (size_t)n * w + O;
    float* fo = Fo + (rb + n) * LDF;
    for (int o = threadIdx.x; o < O; o += blockDim.x) {
        float m = fmaxf(fmaxf(z0[o], z1[o]), fmaxf(z2[o], z3[o]));
        fo[o] = fmaxf(m + zc[o], 0.f);
    }
}

// ---------------- orchestration ----------------
extern "C" void kernel_launch(void* const* d_in, const int* in_sizes, int n_in,
                              void* d_out, int out_size)
{
    const float* x  = (const float*)d_in[0];
    const float* W1 = (const float*)d_in[1];
    const float* W2 = (const float*)d_in[2];
    const float* W3 = (const float*)d_in[3];
    const float* W4 = (const float*)d_in[4];
    const float* W5 = (const float*)d_in[5];
    float* out = (float*)d_out;

    void* p;
    cudaGetSymbolAddress(&p, g_X0);  float* X0 = (float*)p;
    cudaGetSymbolAddress(&p, g_F );  float* F  = (float*)p;
    cudaGetSymbolAddress(&p, g_Z );  float* Z  = (float*)p;
    cudaGetSymbolAddress(&p, g_SQ);  float* SQ = (float*)p;
    cudaGetSymbolAddress(&p, g_ID);  int*   ID = (int*)p;
    cudaGetSymbolAddress(&p, g_C8);  int*   C8 = (int*)p;
    cudaGetSymbolAddress(&p, g_WPf); float* WPf = (float*)p;
    cudaGetSymbolAddress(&p, g_Xb);  __nv_bfloat16* Xb = (__nv_bfloat16*)p;
    cudaGetSymbolAddress(&p, g_Xc);  __nv_bfloat16* Xc = (__nv_bfloat16*)p;
    cudaGetSymbolAddress(&p, g_Wb);  __nv_bfloat16* Wb = (__nv_bfloat16*)p;

    cudaFuncSetAttribute(knn_mma2<64>,
        cudaFuncAttributeMaxDynamicSharedMemorySize, knn2_smem(64));
    cudaFuncSetAttribute(knn_mma2<128>,
        cudaFuncAttributeMaxDynamicSharedMemorySize, knn2_smem(128));
    cudaFuncSetAttribute(gemm_mma,
        cudaFuncAttributeMaxDynamicSharedMemorySize, GSMEM);

    // expanded split patterns (for gemm): A gets {h,h,l}, B gets {h,l,h}
    const unsigned PAT_A = 0u | (0u << 3) | (1u << 6);
    const unsigned PAT_B = 0u | (1u << 3) | (0u << 6);

    tr_x0_k<<<(B_*3*N_ + 255)/256, 256>>>(x, X0);

    // HMMA knn on compact split: split_hl -> knn_mma2 -> exact fixup
    auto knn_tc = [&](const float* Xin, int C) {
        int Kc = 2 * C;
        sqnorm_k<<<(B_*N_*32)/256, 256>>>(Xin, LDF, C, SQ);
        split_hl<<<(B_*N_*Kc + 255)/256, 256>>>(Xin, LDF, C, B_*N_, Xc);
        dim3 kg(N_/128, B_);
        if (C == 64)
            knn_mma2<64> <<<kg, 256, knn2_smem(64) >>>(Xc, SQ, C8);
        else
            knn_mma2<128><<<kg, 256, knn2_smem(128)>>>(Xc, SQ, C8);
        fixup_k<<<(B_*N_)/8, 256>>>(Xin, LDF, C, SQ, C8, ID);
    };

    // ---- layer 1: fp32 knn (C=3) + SIMT z-GEMM
    {
        sqnorm_k<<<(B_*N_*32)/256, 256>>>(X0, 3, 3, SQ);
        knn3_kernel<<<dim3(N_/64, B_), 256>>>(X0, SQ, ID);
        packw_k<<<(2*64*3 + 255)/256, 256>>>(W1, WPf, 64, 3);
        dim3 gg(128/64, (B_*N_)/64, 1);
        gemm_nt<<<gg, 256>>>(3, X0, 3, (size_t)0, WPf, 3, (size_t)0,
                             Z, 128, (size_t)0);
        edge_epi_k<<<dim3(N_, B_), 64>>>(Z, ID, F + 0, 64);
    }

    // ---- layers 2-3: HMMA knn + SIMT fp32 z-GEMM (z feeds next knn)
    auto layer23 = [&](const float* Xin, int C, int O, const float* W, float* Fout) {
        knn_tc(Xin, C);
        packw_k<<<(2*O*C + 255)/256, 256>>>(W, WPf, O, C);
        dim3 gg((2*O)/64, (B_*N_)/64, 1);
        gemm_nt<<<gg, 256>>>(C, Xin, LDF, (size_t)0, WPf, C, (size_t)0,
                             Z, 2*O, (size_t)0);
        edge_epi_k<<<dim3(N_, B_), O>>>(Z, ID, Fout, O);
    };
    layer23(F + 0,  64, 64,  W2, F + 64);    // x2 -> F[:, 64:128]
    layer23(F + 64, 64, 128, W3, F + 128);   // x3 -> F[:, 128:256]

    // ---- layer 4: HMMA knn + HMMA z-GEMM (expanded splits for gemm)
    {
        const int C = 128, O = 256, Kp = 3 * C;       // 384
        knn_tc(F + 128, C);
        packw_k<<<(2*O*C + 255)/256, 256>>>(W4, WPf, O, C);
        split_k<<<(2*O*Kp + 255)/256, 256>>>(WPf, C, C, PAT_B, 3, Kp, 2*O, Wb);
        split_k<<<(B_*N_*Kp + 255)/256, 256>>>(F + 128, LDF, C, PAT_A, 3, Kp, B_*N_, Xb);
        dim3 gg((2*O)/128, (B_*N_)/128, 1);
        gemm_mma<<<gg, 256, GSMEM>>>(Kp, Xb, Kp, (size_t)0, Wb, Kp, (size_t)0,
                                     Z, 2*O, (size_t)0);
        edge_epi_k<<<dim3(N_, B_), O>>>(Z, ID, F + 256, O);
    }

    // ---- final: out[b][o][n] = W5 · concat-features, HMMA
    {
        const int C = 512, Kp = 3 * C;                // 1536
        split_k<<<(512*Kp + 255)/256, 256>>>(W5, C, C, PAT_B, 3, Kp, 512, Wb);
        split_k<<<(B_*N_*Kp + 255)/256, 256>>>(F, LDF, C, PAT_A, 3, Kp, B_*N_, Xb);
        dim3 fg(N_/128, 512/128, B_);
        gemm_mma<<<fg, 256, GSMEM>>>(Kp,
                                     Wb, Kp, (size_t)0,
                                     Xb, Kp, (size_t)N_ * Kp,
                                     out, N_, (size_t)512 * N_);
    }
}

// round 13
// speedup vs baseline: 1.1505x; 1.0181x over previous
#include <cuda_runtime.h>
#include <cuda_bf16.h>
#include <cstdint>
#include <cstddef>

#define B_  8
#define N_  2048
#define LDF 512

// ---------------- scratch (device globals: allocation-free) ----------------
__device__ __align__(16) float g_X0[B_ * N_ * 3];
__device__ __align__(16) float g_F [B_ * N_ * LDF];      // concat features [b][n][512]
__device__ __align__(16) float g_Z [B_ * N_ * LDF];      // z = W' x, rows [m][2O]
__device__ __align__(16) float g_SQ[B_ * N_];
__device__ __align__(16) int   g_ID[B_ * N_ * 4];
__device__ __align__(16) int   g_C8[B_ * N_ * 8];        // knn top-8 candidates
__device__ __align__(16) float g_WPf[512 * 128];         // packed W' fp32 (2O x C)
__device__ __align__(16) __nv_bfloat16 g_Xb[B_ * N_ * 1536]; // compact [h|l] of F (final)
__device__ __align__(16) __nv_bfloat16 g_Xc[B_ * N_ * 256];  // compact [h|l] (knn/L4 act)
__device__ __align__(16) __nv_bfloat16 g_Wb[512 * 1536];     // compact [h|l] weights

__device__ __forceinline__ uint32_t s2u(const void* p) {
    uint32_t a;
    asm("{ .reg .u64 t; cvta.to.shared.u64 t, %1; cvt.u32.u64 %0, t; }" : "=r"(a) : "l"(p));
    return a;
}
// ---- cp.async helpers ----
__device__ __forceinline__ void cp16(uint32_t dst, const void* src) {
    asm volatile("cp.async.cg.shared.global [%0], [%1], 16;" :: "r"(dst), "l"(src));
}
#define CP_COMMIT() asm volatile("cp.async.commit_group;" ::: "memory")
#define CP_WAIT1()  asm volatile("cp.async.wait_group 1;" ::: "memory")

// ---------------- transpose x (B,3,N) -> X0 [b][n][3] ----------------
__global__ void tr_x0_k(const float* __restrict__ x, float* __restrict__ X0)
{
    int t = blockIdx.x * blockDim.x + threadIdx.x;
    const int tot = B_ * 3 * N_;
    if (t >= tot) return;
    int b = t / (3 * N_);
    int r = t % (3 * N_);
    int c = r / N_;
    int n = r % N_;
    X0[((size_t)b * N_ + n) * 3 + c] = x[t];
}

// ---------------- squared norms (L1 only) ----------------
__global__ void sqnorm_k(const float* __restrict__ X, int ldx, int C,
                         float* __restrict__ sq)
{
    int w    = (blockIdx.x * blockDim.x + threadIdx.x) >> 5;
    int lane = threadIdx.x & 31;
    if (w >= B_ * N_) return;
    const float* r = X + (size_t)w * ldx;
    float s = 0.f;
    for (int c = lane; c < C; c += 32) { float v = r[c]; s += v * v; }
    #pragma unroll
    for (int o = 16; o; o >>= 1) s += __shfl_xor_sync(0xffffffffu, s, o);
    if (lane == 0) sq[w] = s;
}

// ------ fused: squared norm + compact [h|l] split, one pass over X --------
__global__ void prep_k(const float* __restrict__ X, int ldx, int C,
                       float* __restrict__ sq, __nv_bfloat16* __restrict__ dst)
{
    int w    = (blockIdx.x * blockDim.x + threadIdx.x) >> 5;
    int lane = threadIdx.x & 31;
    if (w >= B_ * N_) return;
    const float* r = X + (size_t)w * ldx;
    __nv_bfloat16* d = dst + (size_t)w * (2 * C);
    float s = 0.f;
    for (int c = lane; c < C; c += 32) {
        float v = r[c];
        s += v * v;
        float h = __bfloat162float(__float2bfloat16(v));
        d[c]     = __float2bfloat16(h);
        d[C + c] = __float2bfloat16(v - h);
    }
    #pragma unroll
    for (int o = 16; o; o >>= 1) s += __shfl_xor_sync(0xffffffffu, s, o);
    if (lane == 0) sq[w] = s;
}

// ---------------- top-D insertion (value desc, tie: lower index) ----------
template<int D>
__device__ __forceinline__ void topD_insert(float d, int id, float (&v)[D], int (&ix)[D])
{
    if (d > v[D-1] || (d == v[D-1] && id < ix[D-1])) {
        v[D-1] = d; ix[D-1] = id;
        #pragma unroll
        for (int s = D-1; s > 0; s--) {
            if (v[s] > v[s-1] || (v[s] == v[s-1] && ix[s] < ix[s-1])) {
                float tv = v[s]; v[s] = v[s-1]; v[s-1] = tv;
                int   ti = ix[s]; ix[s] = ix[s-1]; ix[s-1] = ti;
            } else break;
        }
    }
}
__device__ __forceinline__ void top4_insert(float d, int id, float (&v)[4], int (&ix)[4])
{ topD_insert<4>(d, id, v, ix); }

// ---------------- fused KNN for C=3 (fp32-exact) --------------------------
__global__ __launch_bounds__(256) void knn3_kernel(const float* __restrict__ X,
                                                   const float* __restrict__ sq,
                                                   int* __restrict__ out_idx)
{
    constexpr int C = 3, QROW = 68;
    __shared__ __align__(16) float pool[64 * 64 * 2];
    float* Qs = pool;
    float* Ks = pool + C * QROW;

    const int b  = blockIdx.y;
    const int q0 = blockIdx.x * 64;
    const int t  = threadIdx.x;
    const int tx = t & 15, ty = t >> 4;
    const size_t rb = (size_t)b * N_;

    for (int f = t; f < 64 * C; f += 256) {
        int c = f % C, m = f / C;
        Qs[c*QROW + m] = X[(rb + q0 + m) * 3 + c];
    }

    float sqq[4];
    #pragma unroll
    for (int i = 0; i < 4; i++) sqq[i] = sq[rb + q0 + ty*4 + i];

    float bv[4][4]; int bix[4][4];
    #pragma unroll
    for (int i = 0; i < 4; i++)
        #pragma unroll
        for (int j = 0; j < 4; j++) { bv[i][j] = -3.4e38f; bix[i][j] = 0x7fffffff; }

    for (int kb = 0; kb < N_; kb += 64) {
        float acc[4][4];
        #pragma unroll
        for (int i = 0; i < 4; i++)
            #pragma unroll
            for (int j = 0; j < 4; j++) acc[i][j] = 0.f;

        __syncthreads();
        for (int f = t; f < 64 * C; f += 256) {
            int c = f % C, m = f / C;
            Ks[c*QROW + m] = X[(rb + kb + m) * 3 + c];
        }
        __syncthreads();
        #pragma unroll
        for (int c = 0; c < C; c++) {
            float4 q4 = *(const float4*)&Qs[c*QROW + ty*4];
            float4 k4 = *(const float4*)&Ks[c*QROW + tx*4];
            float qa[4] = {q4.x, q4.y, q4.z, q4.w};
            float ka[4] = {k4.x, k4.y, k4.z, k4.w};
            #pragma unroll
            for (int i = 0; i < 4; i++)
                #pragma unroll
                for (int j = 0; j < 4; j++)
                    acc[i][j] += qa[i] * ka[j];
        }

        float sqk[4];
        #pragma unroll
        for (int j = 0; j < 4; j++) sqk[j] = sq[rb + kb + tx*4 + j];

        #pragma unroll
        for (int i = 0; i < 4; i++)
            #pragma unroll
            for (int j = 0; j < 4; j++) {
                float d = 2.0f * acc[i][j] - sqq[i] - sqk[j];
                top4_insert(d, kb + tx*4 + j, bv[i], bix[i]);
            }
    }

    __syncthreads();
    float* cv = pool;
    int*   ci = (int*)(pool + 64 * 64);
    #pragma unroll
    for (int qi = 0; qi < 4; qi++) {
        int base = (ty*4 + qi) * 64 + tx * 4;
        #pragma unroll
        for (int r = 0; r < 4; r++) { cv[base + r] = bv[qi][r]; ci[base + r] = bix[qi][r]; }
    }
    __syncthreads();
    if (t < 64) {
        float v4[4]; int i4[4];
        #pragma unroll
        for (int r = 0; r < 4; r++) { v4[r] = -3.4e38f; i4[r] = 0x7fffffff; }
        for (int j = 0; j < 64; j++)
            top4_insert(cv[t*64 + j], ci[t*64 + j], v4, i4);
        int* op = out_idx + (rb + q0 + t) * 4;
        op[0] = i4[0]; op[1] = i4[1]; op[2] = i4[2]; op[3] = i4[3];
    }
}

// ---------------- HMMA helpers ----------------
__device__ __forceinline__ void ldmx4(uint32_t (&r)[4], uint32_t addr)
{
    asm volatile("ldmatrix.sync.aligned.m8n8.x4.shared.b16 {%0,%1,%2,%3}, [%4];"
                 : "=r"(r[0]), "=r"(r[1]), "=r"(r[2]), "=r"(r[3]) : "r"(addr));
}
__device__ __forceinline__ void mma16816(float (&d)[4], const uint32_t (&a)[4],
                                         uint32_t b0, uint32_t b1)
{
    asm volatile(
        "mma.sync.aligned.m16n8k16.row.col.f32.bf16.bf16.f32 "
        "{%0,%1,%2,%3}, {%4,%5,%6,%7}, {%8,%9}, {%0,%1,%2,%3};"
        : "+f"(d[0]), "+f"(d[1]), "+f"(d[2]), "+f"(d[3])
        : "r"(a[0]), "r"(a[1]), "r"(a[2]), "r"(a[3]), "r"(b0), "r"(b1));
}

// ------- compact split: fp32 -> [h | l] bf16 limbs (2C cols) --------------
__global__ void split_hl(const float* __restrict__ src, int lds, int C, int R,
                         __nv_bfloat16* __restrict__ dst)
{
    int t = blockIdx.x * blockDim.x + threadIdx.x;
    int Kc = 2 * C;
    int tot = R * Kc;
    if (t >= tot) return;
    int col = t % Kc;
    int r   = t / Kc;
    int c   = (col < C) ? col : col - C;
    float x = src[(size_t)r * lds + c];
    float h = __bfloat162float(__float2bfloat16(x));
    float v = (col < C) ? h : (x - h);
    dst[t] = __float2bfloat16(v);
}

// ===== HMMA KNN on compact [h|l]: 3-term expansion via chunk addressing ===
template<int C>
__global__ __launch_bounds__(256) void knn_mma2(const __nv_bfloat16* __restrict__ XC,
                                                const float* __restrict__ sq,
                                                int* __restrict__ cand)
{
    constexpr int Kc    = 2 * C;
    constexpr int AKROW = Kc + 8;
    constexpr int BSTG  = 128 * AKROW;
    constexpr int NEXP  = (3 * C) / 64;
    constexpr int NBUF  = (C == 64) ? 3 : 2;
    constexpr int NT    = N_ / 128;
    constexpr int NCP   = Kc / 16;
    extern __shared__ __align__(16) float knnpool[];
    __nv_bfloat16* As = (__nv_bfloat16*)knnpool;
    __nv_bfloat16* Bs = As + BSTG;

    int AOFF[NEXP], BOFF[NEXP];
    if constexpr (C == 64) {
        AOFF[0] = 0;  AOFF[1] = 0;   AOFF[2] = 64;
        BOFF[0] = 0;  BOFF[1] = 64;  BOFF[2] = 0;
    } else {
        AOFF[0] = 0;   AOFF[1] = 64;  AOFF[2] = 0;   AOFF[3] = 64;  AOFF[4] = 128; AOFF[5] = 192;
        BOFF[0] = 0;   BOFF[1] = 64;  BOFF[2] = 128; BOFF[3] = 192; BOFF[4] = 0;   BOFF[5] = 64;
    }

    const int b  = blockIdx.y;
    const int q0 = blockIdx.x * 128;
    const size_t rb = (size_t)b * N_;
    const int t = threadIdx.x, wid = t >> 5, lane = t & 31;
    const int wm = wid & 1, wn = wid >> 1;
    const int gid = lane >> 2, tig = lane & 3;
    const uint32_t uA = s2u(As), uB = s2u(Bs);

    for (int idx = t; idx < 128 * (Kc / 8); idx += 256) {
        int r = idx / (Kc / 8), c8 = idx % (Kc / 8);
        uint4 v = *(const uint4*)(XC + (rb + q0 + r) * (size_t)Kc + c8 * 8);
        *(uint4*)(As + r * AKROW + c8 * 8) = v;
    }
    __syncthreads();

    const int a_r  = wm * 64 + (lane & 15);
    const int a_c8 = (lane >> 4) * 8;
    const int b_rl = wn * 32 + ((lane >> 4) << 3) + (lane & 7);
    const int b_c8 = ((lane >> 3) & 1) * 8;

    float sqq8[8];
    #pragma unroll
    for (int i = 0; i < 8; i++) {
        int mt = i >> 1, h = i & 1;
        sqq8[i] = sq[rb + q0 + wm * 64 + mt * 16 + h * 8 + gid];
    }

    float bv[8][4]; int bix[8][4];
    #pragma unroll
    for (int i = 0; i < 8; i++)
        #pragma unroll
        for (int j = 0; j < 4; j++) { bv[i][j] = -3.4e38f; bix[i][j] = 0x7fffffff; }

    auto kissue = [&](int kt2) {
        if (kt2 < NT) {
            int s = kt2 % NBUF;
            const __nv_bfloat16* p = XC + (rb + kt2 * 128) * (size_t)Kc;
            uint32_t db = uB + 2u * (s * BSTG);
            #pragma unroll
            for (int q = 0; q < NCP; q++) {
                int idx = t + q * 256;
                int r = idx / (Kc / 8), c8 = idx % (Kc / 8);
                cp16(db + 2u * (r * AKROW + c8 * 8),
                     p + (size_t)r * Kc + c8 * 8);
            }
        }
        CP_COMMIT();
    };

    kissue(0); kissue(1);
    for (int kt = 0; kt < NT; kt++) {
        CP_WAIT1();
        __syncthreads();
        const uint32_t uBs = uB + 2u * ((kt % NBUF) * BSTG);

        float acc[4][4][4];
        #pragma unroll
        for (int mt = 0; mt < 4; mt++)
            #pragma unroll
            for (int nt = 0; nt < 4; nt++)
                #pragma unroll
                for (int e = 0; e < 4; e++) acc[mt][nt][e] = 0.f;

        #pragma unroll
        for (int i = 0; i < NEXP; i++) {
            #pragma unroll
            for (int ks = 0; ks < 64; ks += 16) {
                uint32_t af[4][4], bf[2][4];
                #pragma unroll
                for (int mt = 0; mt < 4; mt++)
                    ldmx4(af[mt], uA + 2u * ((a_r + mt * 16) * AKROW + AOFF[i] + ks + a_c8));
                #pragma unroll
                for (int n2 = 0; n2 < 2; n2++)
                    ldmx4(bf[n2], uBs + 2u * ((b_rl + n2 * 16) * AKROW + BOFF[i] + ks + b_c8));
                #pragma unroll
                for (int mt = 0; mt < 4; mt++)
                    #pragma unroll
                    for (int nt = 0; nt < 4; nt++)
                        mma16816(acc[mt][nt], af[mt],
                                 bf[nt >> 1][(nt & 1) * 2], bf[nt >> 1][(nt & 1) * 2 + 1]);
            }
        }
        if constexpr (NBUF == 2) __syncthreads();
        kissue(kt + 2);

        #pragma unroll
        for (int nt = 0; nt < 4; nt++) {
            int c0 = kt * 128 + wn * 32 + nt * 8 + tig * 2;
            float sk0 = sq[rb + c0], sk1 = sq[rb + c0 + 1];
            #pragma unroll
            for (int mt = 0; mt < 4; mt++)
                #pragma unroll
                for (int e = 0; e < 4; e++) {
                    int i8 = mt * 2 + (e >> 1);
                    float d = 2.0f * acc[mt][nt][e] - sqq8[i8] - ((e & 1) ? sk1 : sk0);
                    top4_insert(d, c0 + (e & 1), bv[i8], bix[i8]);
                }
        }
    }

    __syncthreads();
    float* cv = knnpool;
    int*   ci = (int*)(knnpool + 128 * 64);
    #pragma unroll
    for (int i = 0; i < 8; i++) {
        int mt = i >> 1, h = i & 1;
        int rowL = wm * 64 + mt * 16 + h * 8 + gid;
        int slot = wn * 16 + tig * 4;
        #pragma unroll
        for (int j = 0; j < 4; j++) {
            cv[rowL * 64 + slot + j] = bv[i][j];
            ci[rowL * 64 + slot + j] = bix[i][j];
        }
    }
    __syncthreads();
    if (t < 128) {
        float v8[8]; int i8[8];
        #pragma unroll
        for (int r = 0; r < 8; r++) { v8[r] = -3.4e38f; i8[r] = 0x7fffffff; }
        for (int j = 0; j < 64; j++)
            topD_insert<8>(cv[t * 64 + j], ci[t * 64 + j], v8, i8);
        int* op = cand + (rb + q0 + t) * 8;
        #pragma unroll
        for (int r = 0; r < 8; r++) op[r] = i8[r];
    }
}

static inline int knn2_smem(int C) {
    int Kc = 2 * C, row = Kc + 8;
    int nbuf = (C == 64) ? 3 : 2;
    int tot = (1 + nbuf) * 128 * row * 2;
    int mg = 128 * 64 * 8;
    return tot > mg ? tot : mg;
}

// ==== fused: exact fp32 fixup (top8 cand -> top4) + edge epilogue =========
// block (O threads) per point; warp 0 does fixup, all threads gather.
__global__ void fix_epi_k(const float* __restrict__ X, int ldx, int C,
                          const float* __restrict__ sq,
                          const int* __restrict__ cand,
                          const float* __restrict__ Z,
                          float* __restrict__ Fo, int O)
{
    __shared__ int sid[4];
    const int b = blockIdx.y, n = blockIdx.x;
    const size_t rb = (size_t)b * N_;
    const size_t w = rb + n;
    const int t = threadIdx.x, lane = t & 31;

    if (t < 32) {
        int id = 0; float d = -3.4e38f;
        if (lane < 8) {
            id = cand[w * 8 + lane];
            const float* qp = X + w * (size_t)ldx;
            const float* kp = X + (rb + id) * (size_t)ldx;
            float dot = 0.f;
            for (int c = 0; c < C; c += 4) {
                float4 a = *(const float4*)(qp + c);
                float4 b2 = *(const float4*)(kp + c);
                dot += a.x * b2.x + a.y * b2.y + a.z * b2.z + a.w * b2.w;
            }
            d = 2.0f * dot - sq[w] - sq[rb + id];
        }
        float v4[4]; int i4[4];
        #pragma unroll
        for (int r = 0; r < 4; r++) { v4[r] = -3.4e38f; i4[r] = 0x7fffffff; }
        #pragma unroll
        for (int j = 0; j < 8; j++) {
            float dj = __shfl_sync(0xffffffffu, d, j);
            int   ij = __shfl_sync(0xffffffffu, id, j);
            top4_insert(dj, ij, v4, i4);
        }
        if (lane == 0) { sid[0] = i4[0]; sid[1] = i4[1]; sid[2] = i4[2]; sid[3] = i4[3]; }
    }
    __syncthreads();
    int4 id = *(int4*)sid;
    const size_t wz = (size_t)(2 * O);
    const float* zb = Z + rb * wz;
    const float* z0 = zb + (size_t)id.x * wz;
    const float* z1 = zb + (size_t)id.y * wz;
    const float* z2 = zb + (size_t)id.z * wz;
    const float* z3 = zb + (size_t)id.w * wz;
    const float* zc = zb + (size_t)n * wz + O;
    float* fo = Fo + w * LDF;
    for (int o = t; o < O; o += blockDim.x) {
        float m = fmaxf(fmaxf(z0[o], z1[o]), fmaxf(z2[o], z3[o]));
        fo[o] = fmaxf(m + zc[o], 0.f);
    }
}

// ---------------- pack W (O x 2C) -> W' (2O x C) ----------------
__global__ void packw_k(const float* __restrict__ W, float* __restrict__ Wp, int O, int Cc)
{
    int t = blockIdx.x * blockDim.x + threadIdx.x;
    int tot = 2 * O * Cc;
    if (t >= tot) return;
    int r = t / Cc, c = t % Cc;
    Wp[t] = (r < O) ? W[r * (2*Cc) + c] : W[(r - O) * (2*Cc) + Cc + c];
}

// ---------------- SIMT NT SGEMM (precision-critical layers) ----------------
__device__ __forceinline__ void g2s_tile(float* S, const float* M, int ld,
                                         int r0, int k0, int K, int cq, int li)
{
    const float* rp = M + (size_t)(r0 + li) * ld;
    int c = k0 + cq * 4;
    float x, y, z, w;
    if (c + 3 < K && (((uintptr_t)(rp + c) & 15u) == 0)) {
        float4 v = *(const float4*)(rp + c);
        x = v.x; y = v.y; z = v.z; w = v.w;
    } else {
        x = (c + 0 < K) ? rp[c + 0] : 0.f;
        y = (c + 1 < K) ? rp[c + 1] : 0.f;
        z = (c + 2 < K) ? rp[c + 2] : 0.f;
        w = (c + 3 < K) ? rp[c + 3] : 0.f;
    }
    S[(cq*4+0)*68 + li] = x;
    S[(cq*4+1)*68 + li] = y;
    S[(cq*4+2)*68 + li] = z;
    S[(cq*4+3)*68 + li] = w;
}

__global__ __launch_bounds__(256) void gemm_nt(int K,
    const float* __restrict__ A,  int lda, size_t sA,
    const float* __restrict__ Bm, int ldb, size_t sB,
    float* __restrict__ Cm,       int ldc, size_t sC)
{
    __shared__ __align__(16) float As[16 * 68];
    __shared__ __align__(16) float Bs[16 * 68];
    const int bz = blockIdx.z;
    A  += (size_t)bz * sA;
    Bm += (size_t)bz * sB;
    Cm += (size_t)bz * sC;
    const int i0 = blockIdx.y * 64, j0 = blockIdx.x * 64;
    const int t  = threadIdx.x;
    const int tx = t & 15, ty = t >> 4;
    const int cq = t & 3,  li = t >> 2;

    float acc[4][4];
    #pragma unroll
    for (int i = 0; i < 4; i++)
        #pragma unroll
        for (int j = 0; j < 4; j++) acc[i][j] = 0.f;

    for (int k0 = 0; k0 < K; k0 += 16) {
        g2s_tile(As, A,  lda, i0, k0, K, cq, li);
        g2s_tile(Bs, Bm, ldb, j0, k0, K, cq, li);
        __syncthreads();
        #pragma unroll
        for (int c = 0; c < 16; c++) {
            float4 a4 = *(const float4*)&As[c*68 + ty*4];
            float4 b4 = *(const float4*)&Bs[c*68 + tx*4];
            float aa[4] = {a4.x, a4.y, a4.z, a4.w};
            float bb[4] = {b4.x, b4.y, b4.z, b4.w};
            #pragma unroll
            for (int i = 0; i < 4; i++)
                #pragma unroll
                for (int j = 0; j < 4; j++)
                    acc[i][j] += aa[i] * bb[j];
        }
        __syncthreads();
    }
    #pragma unroll
    for (int r = 0; r < 4; r++) {
        float4 v = make_float4(acc[r][0], acc[r][1], acc[r][2], acc[r][3]);
        *(float4*)&Cm[(size_t)(i0 + ty*4 + r) * ldc + j0 + tx*4] = v;
    }
}

// ====== HMMA bf16 NT-GEMM on COMPACT [h|l] operands, 3-term expansion =====
// chunk c (64 K each): tb = c/tpt, inner = (c%tpt)*64;
// offX = inner + limb(selX, tb)*Cc. Chunk order == expanded-buffer order.
#define KC   64
#define KPAD 8
#define AROW (KC + KPAD)
#define GSTG (128 * AROW)
#define GSMEM (3 * GSTG * 2 * 2)

__global__ __launch_bounds__(256) void gemm_mmac(int tpt, int Cc,
    unsigned selA, unsigned selB,
    const __nv_bfloat16* __restrict__ A, int lda, size_t sA,
    const __nv_bfloat16* __restrict__ B, int ldb, size_t sB,
    float* __restrict__ D, int ldd, size_t sD)
{
    extern __shared__ __align__(16) __nv_bfloat16 gsm[];
    __nv_bfloat16* As = gsm;
    __nv_bfloat16* Bs = gsm + 3 * GSTG;
    const int bz = blockIdx.z;
    A += (size_t)bz * sA;
    B += (size_t)bz * sB;
    D += (size_t)bz * sD;
    const int i0 = blockIdx.y * 128;
    const int j0 = blockIdx.x * 128;
    const int t = threadIdx.x, wid = t >> 5, lane = t & 31;
    const int wm = wid & 1, wn = wid >> 1;
    const int gid = lane >> 2, tig = lane & 3;

    const uint32_t uA = s2u(As), uB = s2u(Bs);

    const int a_r  = wm * 64 + (lane & 15);
    const int a_c8 = (lane >> 4) * 8;
    const int b_r  = wn * 32 + ((lane >> 4) << 3) + (lane & 7);
    const int b_c8 = ((lane >> 3) & 1) * 8;

    float acc[4][4][4];
    #pragma unroll
    for (int mt = 0; mt < 4; mt++)
        #pragma unroll
        for (int nt = 0; nt < 4; nt++)
            #pragma unroll
            for (int e = 0; e < 4; e++) acc[mt][nt][e] = 0.f;

    const int nk = 3 * tpt;

    auto issue = [&](int k2) {
        if (k2 < nk) {
            int s = k2 % 3;
            int tb = k2 / tpt, ic = k2 % tpt;
            int offA = ic * 64 + (int)((selA >> tb) & 1u) * Cc;
            int offB = ic * 64 + (int)((selB >> tb) & 1u) * Cc;
            const __nv_bfloat16* Ag = A + (size_t)i0 * lda + offA;
            const __nv_bfloat16* Bg = B + (size_t)j0 * ldb + offB;
            uint32_t da = uA + 2u * (s * GSTG);
            uint32_t db = uB + 2u * (s * GSTG);
            #pragma unroll
            for (int q = 0; q < 4; q++) {
                int idx = t + q * 256;
                int r = idx >> 3, c8 = idx & 7;
                cp16(da + 2u * (r * AROW + c8 * 8), Ag + (size_t)r * lda + c8 * 8);
                cp16(db + 2u * (r * AROW + c8 * 8), Bg + (size_t)r * ldb + c8 * 8);
            }
        }
        CP_COMMIT();
    };

    issue(0); issue(1);
    for (int k = 0; k < nk; k++) {
        CP_WAIT1();
        __syncthreads();
        const int s = k % 3;
        const uint32_t uAs = uA + 2u * (s * GSTG);
        const uint32_t uBs = uB + 2u * (s * GSTG);
        #pragma unroll
        for (int ks = 0; ks < KC; ks += 16) {
            uint32_t af[4][4], bf[2][4];
            #pragma unroll
            for (int mt = 0; mt < 4; mt++)
                ldmx4(af[mt], uAs + 2u * ((a_r + mt * 16) * AROW + ks + a_c8));
            #pragma unroll
            for (int n2 = 0; n2 < 2; n2++)
                ldmx4(bf[n2], uBs + 2u * ((b_r + n2 * 16) * AROW + ks + b_c8));
            #pragma unroll
            for (int mt = 0; mt < 4; mt++)
                #pragma unroll
                for (int nt = 0; nt < 4; nt++)
                    mma16816(acc[mt][nt], af[mt],
                             bf[nt >> 1][(nt & 1) * 2], bf[nt >> 1][(nt & 1) * 2 + 1]);
        }
        issue(k + 2);
    }

    #pragma unroll
    for (int mt = 0; mt < 4; mt++) {
        int r = i0 + wm * 64 + mt * 16 + gid;
        #pragma unroll
        for (int nt = 0; nt < 4; nt++) {
            int c = j0 + wn * 32 + nt * 8 + tig * 2;
            *(float2*)&D[(size_t)r * ldd + c]       = make_float2(acc[mt][nt][0], acc[mt][nt][1]);
            *(float2*)&D[(size_t)(r + 8) * ldd + c] = make_float2(acc[mt][nt][2], acc[mt][nt][3]);
        }
    }
}

// ---------------- gather + relu + max-over-k epilogue (L1) ----------------
__global__ void edge_epi_k(const float* __restrict__ Z, const int* __restrict__ idx,
                           float* __restrict__ Fo, int O)
{
    const int b = blockIdx.y, n = blockIdx.x;
    const size_t rb = (size_t)b * N_;
    int4 id = *(const int4*)(idx + (rb + n) * 4);
    const size_t w = (size_t)(2 * O);
    const float* zb = Z + rb * w;
    const float* z0 = zb + (size_t)id.x * w;
    const float* z1 = zb + (size_t)id.y * w;
    const float* z2 = zb + (size_t)id.z * w;
    const float* z3 = zb + (size_t)id.w * w;
    const float* zc = zb + (size_t)n * w + O;
    float* fo = Fo + (rb + n) * LDF;
    for (int o = threadIdx.x; o < O; o += blockDim.x) {
        float m = fmaxf(fmaxf(z0[o], z1[o]), fmaxf(z2[o], z3[o]));
        fo[o] = fmaxf(m + zc[o], 0.f);
    }
}

// ---------------- orchestration ----------------
extern "C" void kernel_launch(void* const* d_in, const int* in_sizes, int n_in,
                              void* d_out, int out_size)
{
    const float* x  = (const float*)d_in[0];
    const float* W1 = (const float*)d_in[1];
    const float* W2 = (const float*)d_in[2];
    const float* W3 = (const float*)d_in[3];
    const float* W4 = (const float*)d_in[4];
    const float* W5 = (const float*)d_in[5];
    float* out = (float*)d_out;

    void* p;
    cudaGetSymbolAddress(&p, g_X0);  float* X0 = (float*)p;
    cudaGetSymbolAddress(&p, g_F );  float* F  = (float*)p;
    cudaGetSymbolAddress(&p, g_Z );  float* Z  = (float*)p;
    cudaGetSymbolAddress(&p, g_SQ);  float* SQ = (float*)p;
    cudaGetSymbolAddress(&p, g_ID);  int*   ID = (int*)p;
    cudaGetSymbolAddress(&p, g_C8);  int*   C8 = (int*)p;
    cudaGetSymbolAddress(&p, g_WPf); float* WPf = (float*)p;
    cudaGetSymbolAddress(&p, g_Xb);  __nv_bfloat16* Xb = (__nv_bfloat16*)p;
    cudaGetSymbolAddress(&p, g_Xc);  __nv_bfloat16* Xc = (__nv_bfloat16*)p;
    cudaGetSymbolAddress(&p, g_Wb);  __nv_bfloat16* Wb = (__nv_bfloat16*)p;

    cudaFuncSetAttribute(knn_mma2<64>,
        cudaFuncAttributeMaxDynamicSharedMemorySize, knn2_smem(64));
    cudaFuncSetAttribute(knn_mma2<128>,
        cudaFuncAttributeMaxDynamicSharedMemorySize, knn2_smem(128));
    cudaFuncSetAttribute(gemm_mmac,
        cudaFuncAttributeMaxDynamicSharedMemorySize, GSMEM);

    // sel bits per term (0=h,1=l): activations {h,h,l} -> 0b100,
    //                              weights     {h,l,h} -> 0b010
    const unsigned SEL_ACT = 0b100u;
    const unsigned SEL_W   = 0b010u;

    tr_x0_k<<<(B_*3*N_ + 255)/256, 256>>>(x, X0);

    // ---- layer 1: fp32 knn (C=3) + SIMT z-GEMM + plain epilogue
    {
        sqnorm_k<<<(B_*N_*32)/256, 256>>>(X0, 3, 3, SQ);
        knn3_kernel<<<dim3(N_/64, B_), 256>>>(X0, SQ, ID);
        packw_k<<<(2*64*3 + 255)/256, 256>>>(W1, WPf, 64, 3);
        dim3 gg(128/64, (B_*N_)/64, 1);
        gemm_nt<<<gg, 256>>>(3, X0, 3, (size_t)0, WPf, 3, (size_t)0,
                             Z, 128, (size_t)0);
        edge_epi_k<<<dim3(N_, B_), 64>>>(Z, ID, F + 0, 64);
    }

    // ---- layers 2-3: HMMA knn + SIMT fp32 z-GEMM + fused fixup/epilogue
    auto layer23 = [&](const float* Xin, int C, int O, const float* W, float* Fout) {
        prep_k<<<(B_*N_*32)/256, 256>>>(Xin, LDF, C, SQ, Xc);
        dim3 kg(N_/128, B_);
        if (C == 64)
            knn_mma2<64> <<<kg, 256, knn2_smem(64) >>>(Xc, SQ, C8);
        else
            knn_mma2<128><<<kg, 256, knn2_smem(128)>>>(Xc, SQ, C8);
        packw_k<<<(2*O*C + 255)/256, 256>>>(W, WPf, O, C);
        dim3 gg((2*O)/64, (B_*N_)/64, 1);
        gemm_nt<<<gg, 256>>>(C, Xin, LDF, (size_t)0, WPf, C, (size_t)0,
                             Z, 2*O, (size_t)0);
        fix_epi_k<<<dim3(N_, B_), O>>>(Xin, LDF, C, SQ, C8, Z, Fout, O);
    };
    layer23(F + 0,  64, 64,  W2, F + 64);    // x2 -> F[:, 64:128]
    layer23(F + 64, 64, 128, W3, F + 128);   // x3 -> F[:, 128:256]

    // ---- layer 4: HMMA knn + compact HMMA z-GEMM (reuses Xc) -------------
    {
        const int C = 128, O = 256;
        prep_k<<<(B_*N_*32)/256, 256>>>(F + 128, LDF, C, SQ, Xc);
        dim3 kg(N_/128, B_);
        knn_mma2<128><<<kg, 256, knn2_smem(128)>>>(Xc, SQ, C8);
        packw_k<<<(2*O*C + 255)/256, 256>>>(W4, WPf, O, C);
        split_hl<<<(2*O*2*C + 255)/256, 256>>>(WPf, C, C, 2*O, Wb);
        // A = Xc (points, compact C=128), B = Wb (weights, compact)
        dim3 gg((2*O)/128, (B_*N_)/128, 1);
        gemm_mmac<<<gg, 256, GSMEM>>>(C/64, 2*C/2 /*Cc=C*/ == C ? C : C, // Cc = C
                                      SEL_ACT, SEL_W,
                                      Xc, 2*C, (size_t)0,
                                      Wb, 2*C, (size_t)0,
                                      Z, 2*O, (size_t)0);
        fix_epi_k<<<dim3(N_, B_), O>>>(F + 128, LDF, C, SQ, C8, Z, F + 256, O);
    }

    // ---- final: out = W5 · concat-features, compact HMMA ------------------
    {
        const int C = 512;
        split_hl<<<(512*2*C + 255)/256, 256>>>(W5, C, C, 512, Wb);
        split_hl<<<(B_*N_*2*C + 255)/256, 256>>>(F, LDF, C, B_*N_, Xb);
        // A = Wb (weights compact, pattern {h,l,h}), B = Xb (points, {h,h,l})
        dim3 fg(N_/128, 512/128, B_);
        gemm_mmac<<<fg, 256, GSMEM>>>(C/64, C,
                                      SEL_W, SEL_ACT,
                                      Wb, 2*C, (size_t)0,
                                      Xb, 2*C, (size_t)N_ * 2 * C,
                                      out, N_, (size_t)512 * N_);
    }
}

// round 14
// speedup vs baseline: 1.1657x; 1.0132x over previous
#include <cuda_runtime.h>
#include <cuda_bf16.h>
#include <cstdint>
#include <cstddef>

#define B_  8
#define N_  2048
#define LDF 512

// ---------------- scratch (device globals: allocation-free) ----------------
__device__ __align__(16) float g_X0[B_ * N_ * 3];
__device__ __align__(16) float g_F [B_ * N_ * LDF];      // concat features [b][n][512]
__device__ __align__(16) float g_Z [B_ * N_ * LDF];      // z = W' x, rows [m][2O]
__device__ __align__(16) float g_SQ[B_ * N_];
__device__ __align__(16) int   g_ID[B_ * N_ * 4];
__device__ __align__(16) int   g_C8[B_ * N_ * 8];        // knn top-8 candidates
__device__ __align__(16) float g_WPf[512 * 128];         // packed W' fp32 (L1 only)
__device__ __align__(16) __nv_bfloat16 g_Xb[B_ * N_ * 1536]; // compact [h|l] of F (final)
__device__ __align__(16) __nv_bfloat16 g_Xc[B_ * N_ * 256];  // compact [h|l] (knn + z acts)
__device__ __align__(16) __nv_bfloat16 g_Wb[512 * 1536];     // compact [h|l] weights

__device__ __forceinline__ uint32_t s2u(const void* p) {
    uint32_t a;
    asm("{ .reg .u64 t; cvta.to.shared.u64 t, %1; cvt.u32.u64 %0, t; }" : "=r"(a) : "l"(p));
    return a;
}
// ---- cp.async helpers ----
__device__ __forceinline__ void cp16(uint32_t dst, const void* src) {
    asm volatile("cp.async.cg.shared.global [%0], [%1], 16;" :: "r"(dst), "l"(src));
}
#define CP_COMMIT() asm volatile("cp.async.commit_group;" ::: "memory")
#define CP_WAIT1()  asm volatile("cp.async.wait_group 1;" ::: "memory")

// ---------------- transpose x (B,3,N) -> X0 [b][n][3] ----------------
__global__ void tr_x0_k(const float* __restrict__ x, float* __restrict__ X0)
{
    int t = blockIdx.x * blockDim.x + threadIdx.x;
    const int tot = B_ * 3 * N_;
    if (t >= tot) return;
    int b = t / (3 * N_);
    int r = t % (3 * N_);
    int c = r / N_;
    int n = r % N_;
    X0[((size_t)b * N_ + n) * 3 + c] = x[t];
}

// ---------------- squared norms (L1 only) ----------------
__global__ void sqnorm_k(const float* __restrict__ X, int ldx, int C,
                         float* __restrict__ sq)
{
    int w    = (blockIdx.x * blockDim.x + threadIdx.x) >> 5;
    int lane = threadIdx.x & 31;
    if (w >= B_ * N_) return;
    const float* r = X + (size_t)w * ldx;
    float s = 0.f;
    for (int c = lane; c < C; c += 32) { float v = r[c]; s += v * v; }
    #pragma unroll
    for (int o = 16; o; o >>= 1) s += __shfl_xor_sync(0xffffffffu, s, o);
    if (lane == 0) sq[w] = s;
}

// ------ fused: squared norm + compact [h|l] split, one pass over X --------
__global__ void prep_k(const float* __restrict__ X, int ldx, int C,
                       float* __restrict__ sq, __nv_bfloat16* __restrict__ dst)
{
    int w    = (blockIdx.x * blockDim.x + threadIdx.x) >> 5;
    int lane = threadIdx.x & 31;
    if (w >= B_ * N_) return;
    const float* r = X + (size_t)w * ldx;
    __nv_bfloat16* d = dst + (size_t)w * (2 * C);
    float s = 0.f;
    for (int c = lane; c < C; c += 32) {
        float v = r[c];
        s += v * v;
        float h = __bfloat162float(__float2bfloat16(v));
        d[c]     = __float2bfloat16(h);
        d[C + c] = __float2bfloat16(v - h);
    }
    #pragma unroll
    for (int o = 16; o; o >>= 1) s += __shfl_xor_sync(0xffffffffu, s, o);
    if (lane == 0) sq[w] = s;
}

// ------ fused: pack W (O x 2C) -> W' (2O x C) AND compact [h|l] split -----
// dst[r][col]: col<C -> h limb of W'[r][col], col>=C -> l limb of W'[r][col-C]
__global__ void packsplit_k(const float* __restrict__ W, int O, int C,
                            __nv_bfloat16* __restrict__ dst)
{
    int t = blockIdx.x * blockDim.x + threadIdx.x;
    int Kc = 2 * C;
    int tot = 2 * O * Kc;
    if (t >= tot) return;
    int col = t % Kc;
    int r   = t / Kc;
    int c   = (col < C) ? col : col - C;
    float x = (r < O) ? W[r * (2*C) + c] : W[(r - O) * (2*C) + C + c];
    float h = __bfloat162float(__float2bfloat16(x));
    float v = (col < C) ? h : (x - h);
    dst[t] = __float2bfloat16(v);
}

// ---------------- top-D insertion (value desc, tie: lower index) ----------
template<int D>
__device__ __forceinline__ void topD_insert(float d, int id, float (&v)[D], int (&ix)[D])
{
    if (d > v[D-1] || (d == v[D-1] && id < ix[D-1])) {
        v[D-1] = d; ix[D-1] = id;
        #pragma unroll
        for (int s = D-1; s > 0; s--) {
            if (v[s] > v[s-1] || (v[s] == v[s-1] && ix[s] < ix[s-1])) {
                float tv = v[s]; v[s] = v[s-1]; v[s-1] = tv;
                int   ti = ix[s]; ix[s] = ix[s-1]; ix[s-1] = ti;
            } else break;
        }
    }
}
__device__ __forceinline__ void top4_insert(float d, int id, float (&v)[4], int (&ix)[4])
{ topD_insert<4>(d, id, v, ix); }

// ---------------- fused KNN for C=3 (fp32-exact) --------------------------
__global__ __launch_bounds__(256) void knn3_kernel(const float* __restrict__ X,
                                                   const float* __restrict__ sq,
                                                   int* __restrict__ out_idx)
{
    constexpr int C = 3, QROW = 68;
    __shared__ __align__(16) float pool[64 * 64 * 2];
    float* Qs = pool;
    float* Ks = pool + C * QROW;

    const int b  = blockIdx.y;
    const int q0 = blockIdx.x * 64;
    const int t  = threadIdx.x;
    const int tx = t & 15, ty = t >> 4;
    const size_t rb = (size_t)b * N_;

    for (int f = t; f < 64 * C; f += 256) {
        int c = f % C, m = f / C;
        Qs[c*QROW + m] = X[(rb + q0 + m) * 3 + c];
    }

    float sqq[4];
    #pragma unroll
    for (int i = 0; i < 4; i++) sqq[i] = sq[rb + q0 + ty*4 + i];

    float bv[4][4]; int bix[4][4];
    #pragma unroll
    for (int i = 0; i < 4; i++)
        #pragma unroll
        for (int j = 0; j < 4; j++) { bv[i][j] = -3.4e38f; bix[i][j] = 0x7fffffff; }

    for (int kb = 0; kb < N_; kb += 64) {
        float acc[4][4];
        #pragma unroll
        for (int i = 0; i < 4; i++)
            #pragma unroll
            for (int j = 0; j < 4; j++) acc[i][j] = 0.f;

        __syncthreads();
        for (int f = t; f < 64 * C; f += 256) {
            int c = f % C, m = f / C;
            Ks[c*QROW + m] = X[(rb + kb + m) * 3 + c];
        }
        __syncthreads();
        #pragma unroll
        for (int c = 0; c < C; c++) {
            float4 q4 = *(const float4*)&Qs[c*QROW + ty*4];
            float4 k4 = *(const float4*)&Ks[c*QROW + tx*4];
            float qa[4] = {q4.x, q4.y, q4.z, q4.w};
            float ka[4] = {k4.x, k4.y, k4.z, k4.w};
            #pragma unroll
            for (int i = 0; i < 4; i++)
                #pragma unroll
                for (int j = 0; j < 4; j++)
                    acc[i][j] += qa[i] * ka[j];
        }

        float sqk[4];
        #pragma unroll
        for (int j = 0; j < 4; j++) sqk[j] = sq[rb + kb + tx*4 + j];

        #pragma unroll
        for (int i = 0; i < 4; i++)
            #pragma unroll
            for (int j = 0; j < 4; j++) {
                float d = 2.0f * acc[i][j] - sqq[i] - sqk[j];
                top4_insert(d, kb + tx*4 + j, bv[i], bix[i]);
            }
    }

    __syncthreads();
    float* cv = pool;
    int*   ci = (int*)(pool + 64 * 64);
    #pragma unroll
    for (int qi = 0; qi < 4; qi++) {
        int base = (ty*4 + qi) * 64 + tx * 4;
        #pragma unroll
        for (int r = 0; r < 4; r++) { cv[base + r] = bv[qi][r]; ci[base + r] = bix[qi][r]; }
    }
    __syncthreads();
    if (t < 64) {
        float v4[4]; int i4[4];
        #pragma unroll
        for (int r = 0; r < 4; r++) { v4[r] = -3.4e38f; i4[r] = 0x7fffffff; }
        for (int j = 0; j < 64; j++)
            top4_insert(cv[t*64 + j], ci[t*64 + j], v4, i4);
        int* op = out_idx + (rb + q0 + t) * 4;
        op[0] = i4[0]; op[1] = i4[1]; op[2] = i4[2]; op[3] = i4[3];
    }
}

// ---------------- HMMA helpers ----------------
__device__ __forceinline__ void ldmx4(uint32_t (&r)[4], uint32_t addr)
{
    asm volatile("ldmatrix.sync.aligned.m8n8.x4.shared.b16 {%0,%1,%2,%3}, [%4];"
                 : "=r"(r[0]), "=r"(r[1]), "=r"(r[2]), "=r"(r[3]) : "r"(addr));
}
__device__ __forceinline__ void mma16816(float (&d)[4], const uint32_t (&a)[4],
                                         uint32_t b0, uint32_t b1)
{
    asm volatile(
        "mma.sync.aligned.m16n8k16.row.col.f32.bf16.bf16.f32 "
        "{%0,%1,%2,%3}, {%4,%5,%6,%7}, {%8,%9}, {%0,%1,%2,%3};"
        : "+f"(d[0]), "+f"(d[1]), "+f"(d[2]), "+f"(d[3])
        : "r"(a[0]), "r"(a[1]), "r"(a[2]), "r"(a[3]), "r"(b0), "r"(b1));
}

// ------- compact split: fp32 -> [h | l] bf16 limbs (2C cols) --------------
__global__ void split_hl(const float* __restrict__ src, int lds, int C, int R,
                         __nv_bfloat16* __restrict__ dst)
{
    int t = blockIdx.x * blockDim.x + threadIdx.x;
    int Kc = 2 * C;
    int tot = R * Kc;
    if (t >= tot) return;
    int col = t % Kc;
    int r   = t / Kc;
    int c   = (col < C) ? col : col - C;
    float x = src[(size_t)r * lds + c];
    float h = __bfloat162float(__float2bfloat16(x));
    float v = (col < C) ? h : (x - h);
    dst[t] = __float2bfloat16(v);
}

// ===== HMMA KNN on compact [h|l]: 3-term expansion via chunk addressing ===
template<int C>
__global__ __launch_bounds__(256) void knn_mma2(const __nv_bfloat16* __restrict__ XC,
                                                const float* __restrict__ sq,
                                                int* __restrict__ cand)
{
    constexpr int Kc    = 2 * C;
    constexpr int AKROW = Kc + 8;
    constexpr int BSTG  = 128 * AKROW;
    constexpr int NEXP  = (3 * C) / 64;
    constexpr int NBUF  = (C == 64) ? 3 : 2;
    constexpr int NT    = N_ / 128;
    constexpr int NCP   = Kc / 16;
    extern __shared__ __align__(16) float knnpool[];
    __nv_bfloat16* As = (__nv_bfloat16*)knnpool;
    __nv_bfloat16* Bs = As + BSTG;

    int AOFF[NEXP], BOFF[NEXP];
    if constexpr (C == 64) {
        AOFF[0] = 0;  AOFF[1] = 0;   AOFF[2] = 64;
        BOFF[0] = 0;  BOFF[1] = 64;  BOFF[2] = 0;
    } else {
        AOFF[0] = 0;   AOFF[1] = 64;  AOFF[2] = 0;   AOFF[3] = 64;  AOFF[4] = 128; AOFF[5] = 192;
        BOFF[0] = 0;   BOFF[1] = 64;  BOFF[2] = 128; BOFF[3] = 192; BOFF[4] = 0;   BOFF[5] = 64;
    }

    const int b  = blockIdx.y;
    const int q0 = blockIdx.x * 128;
    const size_t rb = (size_t)b * N_;
    const int t = threadIdx.x, wid = t >> 5, lane = t & 31;
    const int wm = wid & 1, wn = wid >> 1;
    const int gid = lane >> 2, tig = lane & 3;
    const uint32_t uA = s2u(As), uB = s2u(Bs);

    for (int idx = t; idx < 128 * (Kc / 8); idx += 256) {
        int r = idx / (Kc / 8), c8 = idx % (Kc / 8);
        uint4 v = *(const uint4*)(XC + (rb + q0 + r) * (size_t)Kc + c8 * 8);
        *(uint4*)(As + r * AKROW + c8 * 8) = v;
    }
    __syncthreads();

    const int a_r  = wm * 64 + (lane & 15);
    const int a_c8 = (lane >> 4) * 8;
    const int b_rl = wn * 32 + ((lane >> 4) << 3) + (lane & 7);
    const int b_c8 = ((lane >> 3) & 1) * 8;

    float sqq8[8];
    #pragma unroll
    for (int i = 0; i < 8; i++) {
        int mt = i >> 1, h = i & 1;
        sqq8[i] = sq[rb + q0 + wm * 64 + mt * 16 + h * 8 + gid];
    }

    float bv[8][4]; int bix[8][4];
    #pragma unroll
    for (int i = 0; i < 8; i++)
        #pragma unroll
        for (int j = 0; j < 4; j++) { bv[i][j] = -3.4e38f; bix[i][j] = 0x7fffffff; }

    auto kissue = [&](int kt2) {
        if (kt2 < NT) {
            int s = kt2 % NBUF;
            const __nv_bfloat16* p = XC + (rb + kt2 * 128) * (size_t)Kc;
            uint32_t db = uB + 2u * (s * BSTG);
            #pragma unroll
            for (int q = 0; q < NCP; q++) {
                int idx = t + q * 256;
                int r = idx / (Kc / 8), c8 = idx % (Kc / 8);
                cp16(db + 2u * (r * AKROW + c8 * 8),
                     p + (size_t)r * Kc + c8 * 8);
            }
        }
        CP_COMMIT();
    };

    kissue(0); kissue(1);
    for (int kt = 0; kt < NT; kt++) {
        CP_WAIT1();
        __syncthreads();
        const uint32_t uBs = uB + 2u * ((kt % NBUF) * BSTG);

        float acc[4][4][4];
        #pragma unroll
        for (int mt = 0; mt < 4; mt++)
            #pragma unroll
            for (int nt = 0; nt < 4; nt++)
                #pragma unroll
                for (int e = 0; e < 4; e++) acc[mt][nt][e] = 0.f;

        #pragma unroll
        for (int i = 0; i < NEXP; i++) {
            #pragma unroll
            for (int ks = 0; ks < 64; ks += 16) {
                uint32_t af[4][4], bf[2][4];
                #pragma unroll
                for (int mt = 0; mt < 4; mt++)
                    ldmx4(af[mt], uA + 2u * ((a_r + mt * 16) * AKROW + AOFF[i] + ks + a_c8));
                #pragma unroll
                for (int n2 = 0; n2 < 2; n2++)
                    ldmx4(bf[n2], uBs + 2u * ((b_rl + n2 * 16) * AKROW + BOFF[i] + ks + b_c8));
                #pragma unroll
                for (int mt = 0; mt < 4; mt++)
                    #pragma unroll
                    for (int nt = 0; nt < 4; nt++)
                        mma16816(acc[mt][nt], af[mt],
                                 bf[nt >> 1][(nt & 1) * 2], bf[nt >> 1][(nt & 1) * 2 + 1]);
            }
        }
        if constexpr (NBUF == 2) __syncthreads();
        kissue(kt + 2);

        #pragma unroll
        for (int nt = 0; nt < 4; nt++) {
            int c0 = kt * 128 + wn * 32 + nt * 8 + tig * 2;
            float sk0 = sq[rb + c0], sk1 = sq[rb + c0 + 1];
            #pragma unroll
            for (int mt = 0; mt < 4; mt++)
                #pragma unroll
                for (int e = 0; e < 4; e++) {
                    int i8 = mt * 2 + (e >> 1);
                    float d = 2.0f * acc[mt][nt][e] - sqq8[i8] - ((e & 1) ? sk1 : sk0);
                    top4_insert(d, c0 + (e & 1), bv[i8], bix[i8]);
                }
        }
    }

    __syncthreads();
    float* cv = knnpool;
    int*   ci = (int*)(knnpool + 128 * 64);
    #pragma unroll
    for (int i = 0; i < 8; i++) {
        int mt = i >> 1, h = i & 1;
        int rowL = wm * 64 + mt * 16 + h * 8 + gid;
        int slot = wn * 16 + tig * 4;
        #pragma unroll
        for (int j = 0; j < 4; j++) {
            cv[rowL * 64 + slot + j] = bv[i][j];
            ci[rowL * 64 + slot + j] = bix[i][j];
        }
    }
    __syncthreads();
    if (t < 128) {
        float v8[8]; int i8[8];
        #pragma unroll
        for (int r = 0; r < 8; r++) { v8[r] = -3.4e38f; i8[r] = 0x7fffffff; }
        for (int j = 0; j < 64; j++)
            topD_insert<8>(cv[t * 64 + j], ci[t * 64 + j], v8, i8);
        int* op = cand + (rb + q0 + t) * 8;
        #pragma unroll
        for (int r = 0; r < 8; r++) op[r] = i8[r];
    }
}

static inline int knn2_smem(int C) {
    int Kc = 2 * C, row = Kc + 8;
    int nbuf = (C == 64) ? 3 : 2;
    int tot = (1 + nbuf) * 128 * row * 2;
    int mg = 128 * 64 * 8;
    return tot > mg ? tot : mg;
}

// ==== fused: exact fp32 fixup (top8 cand -> top4) + edge epilogue =========
__global__ void fix_epi_k(const float* __restrict__ X, int ldx, int C,
                          const float* __restrict__ sq,
                          const int* __restrict__ cand,
                          const float* __restrict__ Z,
                          float* __restrict__ Fo, int O)
{
    __shared__ int sid[4];
    const int b = blockIdx.y, n = blockIdx.x;
    const size_t rb = (size_t)b * N_;
    const size_t w = rb + n;
    const int t = threadIdx.x, lane = t & 31;

    if (t < 32) {
        int id = 0; float d = -3.4e38f;
        if (lane < 8) {
            id = cand[w * 8 + lane];
            const float* qp = X + w * (size_t)ldx;
            const float* kp = X + (rb + id) * (size_t)ldx;
            float dot = 0.f;
            for (int c = 0; c < C; c += 4) {
                float4 a = *(const float4*)(qp + c);
                float4 b2 = *(const float4*)(kp + c);
                dot += a.x * b2.x + a.y * b2.y + a.z * b2.z + a.w * b2.w;
            }
            d = 2.0f * dot - sq[w] - sq[rb + id];
        }
        float v4[4]; int i4[4];
        #pragma unroll
        for (int r = 0; r < 4; r++) { v4[r] = -3.4e38f; i4[r] = 0x7fffffff; }
        #pragma unroll
        for (int j = 0; j < 8; j++) {
            float dj = __shfl_sync(0xffffffffu, d, j);
            int   ij = __shfl_sync(0xffffffffu, id, j);
            top4_insert(dj, ij, v4, i4);
        }
        if (lane == 0) { sid[0] = i4[0]; sid[1] = i4[1]; sid[2] = i4[2]; sid[3] = i4[3]; }
    }
    __syncthreads();
    int4 id = *(int4*)sid;
    const size_t wz = (size_t)(2 * O);
    const float* zb = Z + rb * wz;
    const float* z0 = zb + (size_t)id.x * wz;
    const float* z1 = zb + (size_t)id.y * wz;
    const float* z2 = zb + (size_t)id.z * wz;
    const float* z3 = zb + (size_t)id.w * wz;
    const float* zc = zb + (size_t)n * wz + O;
    float* fo = Fo + w * LDF;
    for (int o = t; o < O; o += blockDim.x) {
        float m = fmaxf(fmaxf(z0[o], z1[o]), fmaxf(z2[o], z3[o]));
        fo[o] = fmaxf(m + zc[o], 0.f);
    }
}

// ---------------- pack W (O x 2C) -> W' (2O x C) fp32 (L1 only) -----------
__global__ void packw_k(const float* __restrict__ W, float* __restrict__ Wp, int O, int Cc)
{
    int t = blockIdx.x * blockDim.x + threadIdx.x;
    int tot = 2 * O * Cc;
    if (t >= tot) return;
    int r = t / Cc, c = t % Cc;
    Wp[t] = (r < O) ? W[r * (2*Cc) + c] : W[(r - O) * (2*Cc) + Cc + c];
}

// ---------------- SIMT NT SGEMM (L1 only, K=3) ----------------------------
__device__ __forceinline__ void g2s_tile(float* S, const float* M, int ld,
                                         int r0, int k0, int K, int cq, int li)
{
    const float* rp = M + (size_t)(r0 + li) * ld;
    int c = k0 + cq * 4;
    float x, y, z, w;
    if (c + 3 < K && (((uintptr_t)(rp + c) & 15u) == 0)) {
        float4 v = *(const float4*)(rp + c);
        x = v.x; y = v.y; z = v.z; w = v.w;
    } else {
        x = (c + 0 < K) ? rp[c + 0] : 0.f;
        y = (c + 1 < K) ? rp[c + 1] : 0.f;
        z = (c + 2 < K) ? rp[c + 2] : 0.f;
        w = (c + 3 < K) ? rp[c + 3] : 0.f;
    }
    S[(cq*4+0)*68 + li] = x;
    S[(cq*4+1)*68 + li] = y;
    S[(cq*4+2)*68 + li] = z;
    S[(cq*4+3)*68 + li] = w;
}

__global__ __launch_bounds__(256) void gemm_nt(int K,
    const float* __restrict__ A,  int lda, size_t sA,
    const float* __restrict__ Bm, int ldb, size_t sB,
    float* __restrict__ Cm,       int ldc, size_t sC)
{
    __shared__ __align__(16) float As[16 * 68];
    __shared__ __align__(16) float Bs[16 * 68];
    const int bz = blockIdx.z;
    A  += (size_t)bz * sA;
    Bm += (size_t)bz * sB;
    Cm += (size_t)bz * sC;
    const int i0 = blockIdx.y * 64, j0 = blockIdx.x * 64;
    const int t  = threadIdx.x;
    const int tx = t & 15, ty = t >> 4;
    const int cq = t & 3,  li = t >> 2;

    float acc[4][4];
    #pragma unroll
    for (int i = 0; i < 4; i++)
        #pragma unroll
        for (int j = 0; j < 4; j++) acc[i][j] = 0.f;

    for (int k0 = 0; k0 < K; k0 += 16) {
        g2s_tile(As, A,  lda, i0, k0, K, cq, li);
        g2s_tile(Bs, Bm, ldb, j0, k0, K, cq, li);
        __syncthreads();
        #pragma unroll
        for (int c = 0; c < 16; c++) {
            float4 a4 = *(const float4*)&As[c*68 + ty*4];
            float4 b4 = *(const float4*)&Bs[c*68 + tx*4];
            float aa[4] = {a4.x, a4.y, a4.z, a4.w};
            float bb[4] = {b4.x, b4.y, b4.z, b4.w};
            #pragma unroll
            for (int i = 0; i < 4; i++)
                #pragma unroll
                for (int j = 0; j < 4; j++)
                    acc[i][j] += aa[i] * bb[j];
        }
        __syncthreads();
    }
    #pragma unroll
    for (int r = 0; r < 4; r++) {
        float4 v = make_float4(acc[r][0], acc[r][1], acc[r][2], acc[r][3]);
        *(float4*)&Cm[(size_t)(i0 + ty*4 + r) * ldc + j0 + tx*4] = v;
    }
}

// ====== HMMA bf16 NT-GEMM on COMPACT [h|l] operands, 3-term expansion =====
#define KC   64
#define KPAD 8
#define AROW (KC + KPAD)
#define GSTG (128 * AROW)
#define GSMEM (3 * GSTG * 2 * 2)

__global__ __launch_bounds__(256) void gemm_mmac(int tpt, int Cc,
    unsigned selA, unsigned selB,
    const __nv_bfloat16* __restrict__ A, int lda, size_t sA,
    const __nv_bfloat16* __restrict__ B, int ldb, size_t sB,
    float* __restrict__ D, int ldd, size_t sD)
{
    extern __shared__ __align__(16) __nv_bfloat16 gsm[];
    __nv_bfloat16* As = gsm;
    __nv_bfloat16* Bs = gsm + 3 * GSTG;
    const int bz = blockIdx.z;
    A += (size_t)bz * sA;
    B += (size_t)bz * sB;
    D += (size_t)bz * sD;
    const int i0 = blockIdx.y * 128;
    const int j0 = blockIdx.x * 128;
    const int t = threadIdx.x, wid = t >> 5, lane = t & 31;
    const int wm = wid & 1, wn = wid >> 1;
    const int gid = lane >> 2, tig = lane & 3;

    const uint32_t uA = s2u(As), uB = s2u(Bs);

    const int a_r  = wm * 64 + (lane & 15);
    const int a_c8 = (lane >> 4) * 8;
    const int b_r  = wn * 32 + ((lane >> 4) << 3) + (lane & 7);
    const int b_c8 = ((lane >> 3) & 1) * 8;

    float acc[4][4][4];
    #pragma unroll
    for (int mt = 0; mt < 4; mt++)
        #pragma unroll
        for (int nt = 0; nt < 4; nt++)
            #pragma unroll
            for (int e = 0; e < 4; e++) acc[mt][nt][e] = 0.f;

    const int nk = 3 * tpt;

    auto issue = [&](int k2) {
        if (k2 < nk) {
            int s = k2 % 3;
            int tb = k2 / tpt, ic = k2 % tpt;
            int offA = ic * 64 + (int)((selA >> tb) & 1u) * Cc;
            int offB = ic * 64 + (int)((selB >> tb) & 1u) * Cc;
            const __nv_bfloat16* Ag = A + (size_t)i0 * lda + offA;
            const __nv_bfloat16* Bg = B + (size_t)j0 * ldb + offB;
            uint32_t da = uA + 2u * (s * GSTG);
            uint32_t db = uB + 2u * (s * GSTG);
            #pragma unroll
            for (int q = 0; q < 4; q++) {
                int idx = t + q * 256;
                int r = idx >> 3, c8 = idx & 7;
                cp16(da + 2u * (r * AROW + c8 * 8), Ag + (size_t)r * lda + c8 * 8);
                cp16(db + 2u * (r * AROW + c8 * 8), Bg + (size_t)r * ldb + c8 * 8);
            }
        }
        CP_COMMIT();
    };

    issue(0); issue(1);
    for (int k = 0; k < nk; k++) {
        CP_WAIT1();
        __syncthreads();
        const int s = k % 3;
        const uint32_t uAs = uA + 2u * (s * GSTG);
        const uint32_t uBs = uB + 2u * (s * GSTG);
        #pragma unroll
        for (int ks = 0; ks < KC; ks += 16) {
            uint32_t af[4][4], bf[2][4];
            #pragma unroll
            for (int mt = 0; mt < 4; mt++)
                ldmx4(af[mt], uAs + 2u * ((a_r + mt * 16) * AROW + ks + a_c8));
            #pragma unroll
            for (int n2 = 0; n2 < 2; n2++)
                ldmx4(bf[n2], uBs + 2u * ((b_r + n2 * 16) * AROW + ks + b_c8));
            #pragma unroll
            for (int mt = 0; mt < 4; mt++)
                #pragma unroll
                for (int nt = 0; nt < 4; nt++)
                    mma16816(acc[mt][nt], af[mt],
                             bf[nt >> 1][(nt & 1) * 2], bf[nt >> 1][(nt & 1) * 2 + 1]);
        }
        issue(k + 2);
    }

    #pragma unroll
    for (int mt = 0; mt < 4; mt++) {
        int r = i0 + wm * 64 + mt * 16 + gid;
        #pragma unroll
        for (int nt = 0; nt < 4; nt++) {
            int c = j0 + wn * 32 + nt * 8 + tig * 2;
            *(float2*)&D[(size_t)r * ldd + c]       = make_float2(acc[mt][nt][0], acc[mt][nt][1]);
            *(float2*)&D[(size_t)(r + 8) * ldd + c] = make_float2(acc[mt][nt][2], acc[mt][nt][3]);
        }
    }
}

// ---------------- gather + relu + max-over-k epilogue (L1) ----------------
__global__ void edge_epi_k(const float* __restrict__ Z, const int* __restrict__ idx,
                           float* __restrict__ Fo, int O)
{
    const int b = blockIdx.y, n = blockIdx.x;
    const size_t rb = (size_t)b * N_;
    int4 id = *(const int4*)(idx + (rb + n) * 4);
    const size_t w = (size_t)(2 * O);
    const float* zb = Z + rb * w;
    const float* z0 = zb + (size_t)id.x * w;
    const float* z1 = zb + (size_t)id.y * w;
    const float* z2 = zb + (size_t)id.z * w;
    const float* z3 = zb + (size_t)id.w * w;
    const float* zc = zb + (size_t)n * w + O;
    float* fo = Fo + (rb + n) * LDF;
    for (int o = threadIdx.x; o < O; o += blockDim.x) {
        float m = fmaxf(fmaxf(z0[o], z1[o]), fmaxf(z2[o], z3[o]));
        fo[o] = fmaxf(m + zc[o], 0.f);
    }
}

// ---------------- orchestration ----------------
extern "C" void kernel_launch(void* const* d_in, const int* in_sizes, int n_in,
                              void* d_out, int out_size)
{
    const float* x  = (const float*)d_in[0];
    const float* W1 = (const float*)d_in[1];
    const float* W2 = (const float*)d_in[2];
    const float* W3 = (const float*)d_in[3];
    const float* W4 = (const float*)d_in[4];
    const float* W5 = (const float*)d_in[5];
    float* out = (float*)d_out;

    void* p;
    cudaGetSymbolAddress(&p, g_X0);  float* X0 = (float*)p;
    cudaGetSymbolAddress(&p, g_F );  float* F  = (float*)p;
    cudaGetSymbolAddress(&p, g_Z );  float* Z  = (float*)p;
    cudaGetSymbolAddress(&p, g_SQ);  float* SQ = (float*)p;
    cudaGetSymbolAddress(&p, g_ID);  int*   ID = (int*)p;
    cudaGetSymbolAddress(&p, g_C8);  int*   C8 = (int*)p;
    cudaGetSymbolAddress(&p, g_WPf); float* WPf = (float*)p;
    cudaGetSymbolAddress(&p, g_Xb);  __nv_bfloat16* Xb = (__nv_bfloat16*)p;
    cudaGetSymbolAddress(&p, g_Xc);  __nv_bfloat16* Xc = (__nv_bfloat16*)p;
    cudaGetSymbolAddress(&p, g_Wb);  __nv_bfloat16* Wb = (__nv_bfloat16*)p;

    cudaFuncSetAttribute(knn_mma2<64>,
        cudaFuncAttributeMaxDynamicSharedMemorySize, knn2_smem(64));
    cudaFuncSetAttribute(knn_mma2<128>,
        cudaFuncAttributeMaxDynamicSharedMemorySize, knn2_smem(128));
    cudaFuncSetAttribute(gemm_mmac,
        cudaFuncAttributeMaxDynamicSharedMemorySize, GSMEM);

    // sel bits per term (0=h,1=l): activations {h,h,l} -> 0b100,
    //                              weights     {h,l,h} -> 0b010
    const unsigned SEL_ACT = 0b100u;
    const unsigned SEL_W   = 0b010u;

    tr_x0_k<<<(B_*3*N_ + 255)/256, 256>>>(x, X0);

    // ---- layer 1: fp32 knn (C=3) + SIMT z-GEMM + plain epilogue
    {
        sqnorm_k<<<(B_*N_*32)/256, 256>>>(X0, 3, 3, SQ);
        knn3_kernel<<<dim3(N_/64, B_), 256>>>(X0, SQ, ID);
        packw_k<<<(2*64*3 + 255)/256, 256>>>(W1, WPf, 64, 3);
        dim3 gg(128/64, (B_*N_)/64, 1);
        gemm_nt<<<gg, 256>>>(3, X0, 3, (size_t)0, WPf, 3, (size_t)0,
                             Z, 128, (size_t)0);
        edge_epi_k<<<dim3(N_, B_), 64>>>(Z, ID, F + 0, 64);
    }

    // ---- layers 2-4: HMMA knn + compact HMMA z-GEMM (reuses Xc) ----------
    auto layer_tc = [&](const float* Xin, int C, int O, const float* W, float* Fout) {
        prep_k<<<(B_*N_*32)/256, 256>>>(Xin, LDF, C, SQ, Xc);
        dim3 kg(N_/128, B_);
        if (C == 64)
            knn_mma2<64> <<<kg, 256, knn2_smem(64) >>>(Xc, SQ, C8);
        else
            knn_mma2<128><<<kg, 256, knn2_smem(128)>>>(Xc, SQ, C8);
        packsplit_k<<<(2*O*2*C + 255)/256, 256>>>(W, O, C, Wb);
        dim3 gg((2*O)/128, (B_*N_)/128, 1);
        gemm_mmac<<<gg, 256, GSMEM>>>(C/64, C, SEL_ACT, SEL_W,
                                      Xc, 2*C, (size_t)0,
                                      Wb, 2*C, (size_t)0,
                                      Z, 2*O, (size_t)0);
        fix_epi_k<<<dim3(N_, B_), O>>>(Xin, LDF, C, SQ, C8, Z, Fout, O);
    };
    layer_tc(F + 0,   64,  64,  W2, F + 64);    // x2 -> F[:, 64:128]
    layer_tc(F + 64,  64,  128, W3, F + 128);   // x3 -> F[:, 128:256]
    layer_tc(F + 128, 128, 256, W4, F + 256);   // x4 -> F[:, 256:512]

    // ---- final: out = W5 · concat-features, compact HMMA ------------------
    {
        const int C = 512;
        split_hl<<<(512*2*C + 255)/256, 256>>>(W5, C, C, 512, Wb);
        split_hl<<<(B_*N_*2*C + 255)/256, 256>>>(F, LDF, C, B_*N_, Xb);
        dim3 fg(N_/128, 512/128, B_);
        gemm_mmac<<<fg, 256, GSMEM>>>(C/64, C,
                                      SEL_W, SEL_ACT,
                                      Wb, 2*C, (size_t)0,
                                      Xb, 2*C, (size_t)N_ * 2 * C,
                                      out, N_, (size_t)512 * N_);
    }
}